// round 13
// baseline (speedup 1.0000x reference)
#include <cuda_runtime.h>
#include <cuda_fp16.h>
#include <math.h>
#include <stdint.h>

// ---------------- problem constants ----------------
#define Lq     2048
#define HIDm   4096
#define Hh     128
#define Pp     64
#define Nn     128
#define Gg     8
#define Kk     4
#define CSz    256
#define NC     8            // L / CS
#define INTERC 8192         // H*P
#define CONVC  10240        // INTER + 2*G*N
#define PROJC  18560        // INTER + CONV + H
#define GSZ    1024         // INTER / G
#define EPSf   1e-5f

// ---------------- scratch (static device globals; no allocation) ----------------
__device__ float d_proj[(size_t)Lq * PROJC];
__device__ float d_xbc [(size_t)Lq * CONVC];
__device__ float d_dt  [(size_t)Lq * Hh];
__device__ float d_cum [(size_t)Lq * Hh];
__device__ float d_y   [(size_t)Lq * INTERC];
__device__ float d_st  [(size_t)NC * Hh * Pp * Nn];
// fp16 operands
__device__ __align__(16) __half d_ha   [(size_t)Lq * HIDm];
__device__ __align__(16) __half d_hb1  [(size_t)PROJC * HIDm];
__device__ __align__(16) __half d_hb2  [(size_t)HIDm * INTERC];
__device__ __align__(16) __half d_gh   [(size_t)Lq * INTERC];
__device__ __align__(16) __half d_xbch [(size_t)Lq * CONVC];
__device__ __align__(16) __half d_prevh[(size_t)NC * Hh * Pp * Nn];

__device__ __forceinline__ uint32_t smem_u32(const void* p) {
    return (uint32_t)__cvta_generic_to_shared(p);
}
__device__ __forceinline__ void cp16(uint32_t dst, const void* src) {
    asm volatile("cp.async.cg.shared.global [%0], [%1], 16;\n" :: "r"(dst), "l"(src));
}
__device__ __forceinline__ void mma_f16(float* c, const uint32_t* a, const uint32_t* b) {
    asm volatile(
        "mma.sync.aligned.m16n8k16.row.col.f32.f16.f16.f32 "
        "{%0,%1,%2,%3}, {%4,%5,%6,%7}, {%8,%9}, {%0,%1,%2,%3};"
        : "+f"(c[0]), "+f"(c[1]), "+f"(c[2]), "+f"(c[3])
        : "r"(a[0]), "r"(a[1]), "r"(a[2]), "r"(a[3]), "r"(b[0]), "r"(b[1]));
}
__device__ __forceinline__ void ldm_x4(uint32_t* r, uint32_t addr) {
    asm volatile("ldmatrix.sync.aligned.m8n8.x4.shared.b16 {%0,%1,%2,%3}, [%4];"
                 : "=r"(r[0]), "=r"(r[1]), "=r"(r[2]), "=r"(r[3]) : "r"(addr));
}

// ---------------- merged fp32 -> fp16 pre-convert (grid-stride, 3 segments) ----------------
#define N4_A  (Lq * HIDm / 4)
#define N4_B1 (PROJC * HIDm / 4)
#define N4_B2 (HIDm * INTERC / 4)
__global__ void __launch_bounds__(256)
cvt_all_k(const float4* __restrict__ inA, uint2* __restrict__ outA,
          const float4* __restrict__ inB1, uint2* __restrict__ outB1,
          const float4* __restrict__ inB2, uint2* __restrict__ outB2) {
    const int total = N4_A + N4_B1 + N4_B2;
    for (int i = blockIdx.x * 256 + threadIdx.x; i < total; i += gridDim.x * 256) {
        const float4* src;
        uint2* dst;
        int idx;
        if (i < N4_A)            { src = inA;  dst = outA;  idx = i; }
        else if (i < N4_A + N4_B1) { src = inB1; dst = outB1; idx = i - N4_A; }
        else                     { src = inB2; dst = outB2; idx = i - N4_A - N4_B1; }
        float4 v = src[idx];
        __half2 lo = __floats2half2_rn(v.x, v.y);
        __half2 hi = __floats2half2_rn(v.z, v.w);
        uint2 o;
        o.x = *(const uint32_t*)&lo;
        o.y = *(const uint32_t*)&hi;
        dst[idx] = o;
    }
}

// =====================================================================
//  fp16 mma GEMM (R7 config, frozen)
// =====================================================================
#define BMt 128
#define BNt 128
#define BKh 64
#define PADh 72
#define STAGE_H ((BMt + BNt) * PADh)
#define GM_SMEM (3 * STAGE_H * 2)

__device__ __forceinline__ void gemm_f16_body(const __half* __restrict__ A,
                                              const __half* __restrict__ B,
                                              float* __restrict__ C,
                                              int Ncols, int K) {
    extern __shared__ __half smh[];
    const uint32_t sbase = smem_u32(smh);
    const int tid = threadIdx.x, wid = tid >> 5, lane = tid & 31;
    const int g = lane >> 2, q = lane & 3;
    const int m0 = blockIdx.x * BMt;
    const int n0 = blockIdx.y * BNt;
    const int wm = (wid >> 1) * 32;
    const int wn = (wid & 1) * 64;
    const int nk = K / BKh;

    const int a_row = wm + (lane & 15);
    const int a_kh  = ((lane >> 4) & 1) * 8;
    const uint32_t a_off = (uint32_t)(a_row * PADh + a_kh) * 2;
    const int b_nrow = (lane & 7) + ((lane >> 4) & 1) * 8;
    const int b_kh   = ((lane >> 3) & 1) * 8;
    const uint32_t b_off = (uint32_t)(BMt * PADh + (wn + b_nrow) * PADh + b_kh) * 2;

    float acc[2][8][4];
#pragma unroll
    for (int i = 0; i < 2; ++i)
#pragma unroll
        for (int j = 0; j < 8; ++j)
#pragma unroll
            for (int r = 0; r < 4; ++r) acc[i][j][r] = 0.f;

    auto load_stage = [&](int c) {
        const int s = c % 3;
        const int k0 = c * BKh;
        const uint32_t abase = sbase + s * STAGE_H * 2;
        const uint32_t bbase = abase + BMt * PADh * 2;
#pragma unroll
        for (int i = 0; i < 4; ++i) {
            int t = tid + i * 256;
            int r = t >> 3, qq = t & 7;
            cp16(abase + (uint32_t)(r * PADh + qq * 8) * 2,
                 A + (size_t)(m0 + r) * K + k0 + qq * 8);
        }
#pragma unroll
        for (int i = 0; i < 4; ++i) {
            int t = tid + i * 256;
            int r = t >> 3, qq = t & 7;
            cp16(bbase + (uint32_t)(r * PADh + qq * 8) * 2,
                 B + (size_t)(n0 + r) * K + k0 + qq * 8);
        }
        asm volatile("cp.async.commit_group;");
    };

    load_stage(0);
    load_stage(1);

    for (int c = 0; c < nk; ++c) {
        if (c + 1 < nk) {
            asm volatile("cp.async.wait_group 1;");
        } else {
            asm volatile("cp.async.wait_group 0;");
        }
        __syncthreads();

        if (c + 2 < nk) load_stage(c + 2);

        const uint32_t stg = sbase + (uint32_t)(c % 3) * STAGE_H * 2;
        const uint32_t a_addr = stg + a_off;
        const uint32_t b_addr = stg + b_off;

#pragma unroll
        for (int ks = 0; ks < 4; ++ks) {
            const uint32_t kadd = (uint32_t)ks * 32;
            uint32_t af[2][4];
            ldm_x4(af[0], a_addr + kadd);
            ldm_x4(af[1], a_addr + 16 * PADh * 2 + kadd);
            uint32_t bf[4][4];
#pragma unroll
            for (int nb = 0; nb < 4; ++nb)
                ldm_x4(bf[nb], b_addr + (uint32_t)(nb * 16 * PADh) * 2 + kadd);
#pragma unroll
            for (int mi = 0; mi < 2; ++mi)
#pragma unroll
                for (int ni = 0; ni < 8; ++ni)
                    mma_f16(acc[mi][ni], af[mi], &bf[ni >> 1][(ni & 1) * 2]);
        }
    }

#pragma unroll
    for (int mi = 0; mi < 2; ++mi) {
        const int r = m0 + wm + mi * 16 + g;
#pragma unroll
        for (int ni = 0; ni < 8; ++ni) {
            const int cb = n0 + wn + ni * 8 + 2 * q;
            *(float2*)(C + (size_t)r * Ncols + cb) =
                make_float2(acc[mi][ni][0], acc[mi][ni][1]);
            *(float2*)(C + (size_t)(r + 8) * Ncols + cb) =
                make_float2(acc[mi][ni][2], acc[mi][ni][3]);
        }
    }
}

__global__ void __launch_bounds__(256, 2)
gemm1_mma_k() { gemm_f16_body(d_ha, d_hb1, d_proj, PROJC, HIDm); }
__global__ void __launch_bounds__(256, 2)
gemm2_mma_k(float* __restrict__ C) { gemm_f16_body(d_gh, d_hb2, C, HIDm, INTERC); }

// ---------------- fused: conv+SiLU (float4, f32 + f16 mirror) || dt warp-scan ----------------
// grid (11, Lq): x<10 -> conv (4 ch/thread); x==10 && y<1024 -> dt (h=y&127, c=y>>7)
__global__ void __launch_bounds__(256)
conv_dt_k(const float* __restrict__ w, const float* __restrict__ b,
          const float* __restrict__ dt_bias, const float* __restrict__ A_log) {
    if (blockIdx.x < 10) {
        int c = (blockIdx.x * 256 + threadIdx.x) * 4;
        int l = blockIdx.y;
        float4 w0 = *(const float4*)&w[(c + 0) * 4];
        float4 w1 = *(const float4*)&w[(c + 1) * 4];
        float4 w2 = *(const float4*)&w[(c + 2) * 4];
        float4 w3 = *(const float4*)&w[(c + 3) * 4];
        float4 acc = *(const float4*)&b[c];
#pragma unroll
        for (int k = 0; k < Kk; ++k) {
            int ls = l - (Kk - 1) + k;
            if (ls >= 0) {
                float4 pv = *(const float4*)&d_proj[(size_t)ls * PROJC + INTERC + c];
                acc.x += ((const float*)&w0)[k] * pv.x;
                acc.y += ((const float*)&w1)[k] * pv.y;
                acc.z += ((const float*)&w2)[k] * pv.z;
                acc.w += ((const float*)&w3)[k] * pv.w;
            }
        }
        acc.x = acc.x / (1.f + __expf(-acc.x));
        acc.y = acc.y / (1.f + __expf(-acc.y));
        acc.z = acc.z / (1.f + __expf(-acc.z));
        acc.w = acc.w / (1.f + __expf(-acc.w));
        *(float4*)&d_xbc[(size_t)l * CONVC + c] = acc;
        __half2 lo = __floats2half2_rn(acc.x, acc.y);
        __half2 hi = __floats2half2_rn(acc.z, acc.w);
        uint2 o;
        o.x = *(const uint32_t*)&lo;
        o.y = *(const uint32_t*)&hi;
        *(uint2*)&d_xbch[(size_t)l * CONVC + c] = o;
    } else {
        if (blockIdx.y >= 1024) return;
        int h = blockIdx.y & 127, c = blockIdx.y >> 7, t = threadIdx.x;
        int lane = t & 31, warp = t >> 5;
        int l = c * CSz + t;
        float x = d_proj[(size_t)l * PROJC + (INTERC + CONVC) + h] + dt_bias[h];
        float sp = fmaxf(x, 0.f) + log1pf(expf(-fabsf(x)));
        float dtv = fmaxf(sp, 0.f);
        float A = -expf(A_log[h]);
        float val = dtv * A;
        // warp inclusive scan
#pragma unroll
        for (int o = 1; o < 32; o <<= 1) {
            float n = __shfl_up_sync(0xffffffffu, val, o);
            if (lane >= o) val += n;
        }
        __shared__ float wsum[8];
        if (lane == 31) wsum[warp] = val;
        __syncthreads();
        if (warp == 0 && lane < 8) {
            float v = wsum[lane];
#pragma unroll
            for (int o = 1; o < 8; o <<= 1) {
                float n = __shfl_up_sync(0xffu, v, o);
                if (lane >= o) v += n;
            }
            wsum[lane] = v;
        }
        __syncthreads();
        float base = (warp > 0) ? wsum[warp - 1] : 0.f;
        d_dt [(size_t)l * Hh + h] = dtv;
        d_cum[(size_t)l * Hh + h] = val + base;
    }
}

// ---------------- fused: intra-chunk (fp16 MMA) || chunk-states (fp32) ----------------
#define CW 136
#define SW 72
#define IT_HALVES (64 * (2 * CW + 3 * SW))
#define IT_SMEM2  (IT_HALVES * 2 + 3 * 64 * 4)
__global__ void __launch_bounds__(256, 2)
ssd_intra_states_k() {
    extern __shared__ __align__(16) char sraw[];
    const int h = blockIdx.y, c = blockIdx.z;
    const int g = h >> 4;
    const int tid = threadIdx.x;

    if (blockIdx.x < 4) {
        __half* Cs  = (__half*)sraw;
        __half* Bs  = Cs + 64 * CW;
        __half* Ss  = Bs + 64 * CW;
        __half* Xs  = Ss + 64 * SW;
        __half* XsT = Xs + 64 * SW;
        float* cum_i = (float*)(XsT + 64 * SW);
        float* cum_j = cum_i + 64;
        float* dtj   = cum_j + 64;

        const int it = blockIdx.x;
        const int li0 = c * CSz + it * 64;
        const int ccol = INTERC + Gg * Nn + g * Nn;
        const int bcol = INTERC + g * Nn;

        const int wid = tid >> 5, lane = tid & 31;
        const int gq = lane >> 2, q = lane & 3;
        const int mw = wid >> 1;
        const int nw = wid & 1;

        const uint32_t CsB = smem_u32(Cs), BsB = smem_u32(Bs);
        const uint32_t SsB = smem_u32(Ss), XtB = smem_u32(XsT);
        const uint32_t aS_off = (uint32_t)((mw * 16 + (lane & 15)) * CW + ((lane >> 4) & 1) * 8) * 2;
        const uint32_t bS_off = (uint32_t)((nw * 32 + (lane & 7) + ((lane >> 4) & 1) * 8) * CW + ((lane >> 3) & 1) * 8) * 2;
        const uint32_t aY_off = (uint32_t)((mw * 16 + (lane & 15)) * SW + ((lane >> 4) & 1) * 8) * 2;
        const uint32_t bY_off = (uint32_t)((nw * 32 + (lane & 7) + ((lane >> 4) & 1) * 8) * SW + ((lane >> 3) & 1) * 8) * 2;

#pragma unroll
        for (int rep = 0; rep < 4; ++rep) {
            int idx = tid + rep * 256;
            int r = idx >> 4, qq = idx & 15;
            *(uint4*)&Cs[r * CW + qq * 8] =
                *(const uint4*)&d_xbch[(size_t)(li0 + r) * CONVC + ccol + qq * 8];
        }
        if (tid < 64) cum_i[tid] = d_cum[(size_t)(li0 + tid) * Hh + h];

        float accY[4][4];
#pragma unroll
        for (int i = 0; i < 4; ++i)
#pragma unroll
            for (int j = 0; j < 4; ++j) accY[i][j] = 0.f;

        const int i0 = mw * 16 + gq;

        for (int jt = 0; jt <= it; ++jt) {
            const int lj0 = c * CSz + jt * 64;
            __syncthreads();
#pragma unroll
            for (int rep = 0; rep < 4; ++rep) {
                int idx = tid + rep * 256;
                int r = idx >> 4, qq = idx & 15;
                *(uint4*)&Bs[r * CW + qq * 8] =
                    *(const uint4*)&d_xbch[(size_t)(lj0 + r) * CONVC + bcol + qq * 8];
            }
#pragma unroll
            for (int rep = 0; rep < 2; ++rep) {
                int idx = tid + rep * 256;
                int r = idx >> 3, qq = idx & 7;
                *(uint4*)&Xs[r * SW + qq * 8] =
                    *(const uint4*)&d_xbch[(size_t)(lj0 + r) * CONVC + h * Pp + qq * 8];
            }
            if (tid < 64) {
                cum_j[tid] = d_cum[(size_t)(lj0 + tid) * Hh + h];
                dtj  [tid] = d_dt [(size_t)(lj0 + tid) * Hh + h];
            }
            __syncthreads();

#pragma unroll
            for (int rep = 0; rep < 4; ++rep) {
                int idx = tid + rep * 256;
                int bb = idx >> 5, aa = idx & 31;
                uint32_t u0 = *(uint32_t*)&Xs[(2 * bb) * SW + 2 * aa];
                uint32_t u1 = *(uint32_t*)&Xs[(2 * bb + 1) * SW + 2 * aa];
                uint32_t lo = (u0 & 0xffffu) | (u1 << 16);
                uint32_t hi = (u0 >> 16) | (u1 & 0xffff0000u);
                *(uint32_t*)&XsT[(2 * aa) * SW + 2 * bb] = lo;
                *(uint32_t*)&XsT[(2 * aa + 1) * SW + 2 * bb] = hi;
            }

            float accS[4][4];
#pragma unroll
            for (int i = 0; i < 4; ++i)
#pragma unroll
                for (int j = 0; j < 4; ++j) accS[i][j] = 0.f;
#pragma unroll
            for (int ks = 0; ks < 8; ++ks) {
                const uint32_t kadd = (uint32_t)ks * 32;
                uint32_t af[4];
                ldm_x4(af, CsB + aS_off + kadd);
                uint32_t bf[2][4];
                ldm_x4(bf[0], BsB + bS_off + kadd);
                ldm_x4(bf[1], BsB + bS_off + (uint32_t)(16 * CW) * 2 + kadd);
#pragma unroll
                for (int ni = 0; ni < 4; ++ni)
                    mma_f16(accS[ni], af, &bf[ni >> 1][(ni & 1) * 2]);
            }

            {
                const float ci0 = cum_i[i0], ci1 = cum_i[i0 + 8];
                const int gi0 = it * 64 + i0, gi1 = gi0 + 8;
#pragma unroll
                for (int ni = 0; ni < 4; ++ni) {
                    int jb = nw * 32 + ni * 8 + 2 * q;
                    float cj0 = cum_j[jb], cj1 = cum_j[jb + 1];
                    float dj0 = dtj[jb],  dj1 = dtj[jb + 1];
                    int gj0 = jt * 64 + jb, gj1 = gj0 + 1;
                    float v00 = (gi0 >= gj0) ? accS[ni][0] * __expf(ci0 - cj0) * dj0 : 0.f;
                    float v01 = (gi0 >= gj1) ? accS[ni][1] * __expf(ci0 - cj1) * dj1 : 0.f;
                    float v10 = (gi1 >= gj0) ? accS[ni][2] * __expf(ci1 - cj0) * dj0 : 0.f;
                    float v11 = (gi1 >= gj1) ? accS[ni][3] * __expf(ci1 - cj1) * dj1 : 0.f;
                    __half2 h0 = __floats2half2_rn(v00, v01);
                    __half2 h1 = __floats2half2_rn(v10, v11);
                    *(__half2*)&Ss[i0 * SW + jb] = h0;
                    *(__half2*)&Ss[(i0 + 8) * SW + jb] = h1;
                }
            }
            __syncthreads();

#pragma unroll
            for (int ks = 0; ks < 4; ++ks) {
                const uint32_t kadd = (uint32_t)ks * 32;
                uint32_t af[4];
                ldm_x4(af, SsB + aY_off + kadd);
                uint32_t bf[2][4];
                ldm_x4(bf[0], XtB + bY_off + kadd);
                ldm_x4(bf[1], XtB + bY_off + (uint32_t)(16 * SW) * 2 + kadd);
#pragma unroll
                for (int ni = 0; ni < 4; ++ni)
                    mma_f16(accY[ni], af, &bf[ni >> 1][(ni & 1) * 2]);
            }
        }

#pragma unroll
        for (int ni = 0; ni < 4; ++ni) {
            int p = nw * 32 + ni * 8 + 2 * q;
            *(float2*)&d_y[(size_t)(li0 + i0) * INTERC + h * Pp + p] =
                make_float2(accY[ni][0], accY[ni][1]);
            *(float2*)&d_y[(size_t)(li0 + i0 + 8) * INTERC + h * Pp + p] =
                make_float2(accY[ni][2], accY[ni][3]);
        }
    } else {
        // ================= states branch (fp32, unchanged) =================
        float* Xs  = (float*)sraw;
        float* Bsh = Xs + 32 * 68;
        float* ws  = Bsh + 32 * 132;
        const int tx = tid & 15, ty = tid >> 4;

        float acc[4][8];
#pragma unroll
        for (int i = 0; i < 4; ++i)
#pragma unroll
            for (int j = 0; j < 8; ++j) acc[i][j] = 0.f;

        const float cum_last = d_cum[(size_t)(c * CSz + CSz - 1) * Hh + h];

        for (int j0 = 0; j0 < CSz; j0 += 32) {
            __syncthreads();
#pragma unroll
            for (int rep = 0; rep < 2; ++rep) {
                int idx = tid + rep * 256;
                int r = idx >> 4, qn = idx & 15;
                *(float4*)&Xs[r * 68 + qn * 4] =
                    *(const float4*)(&d_xbc[(size_t)(c * CSz + j0 + r) * CONVC + h * Pp + qn * 4]);
            }
#pragma unroll
            for (int rep = 0; rep < 4; ++rep) {
                int idx = tid + rep * 256;
                int r = idx >> 5, qn = idx & 31;
                *(float4*)&Bsh[r * 132 + qn * 4] =
                    *(const float4*)(&d_xbc[(size_t)(c * CSz + j0 + r) * CONVC + INTERC + g * Nn + qn * 4]);
            }
            if (tid < 32) {
                int l = c * CSz + j0 + tid;
                ws[tid] = d_dt[(size_t)l * Hh + h] * __expf(cum_last - d_cum[(size_t)l * Hh + h]);
            }
            __syncthreads();
#pragma unroll 4
            for (int j = 0; j < 32; ++j) {
                float w = ws[j];
                float4 a4 = *(const float4*)&Xs[j * 68 + ty * 4];
                float aw[4] = {a4.x * w, a4.y * w, a4.z * w, a4.w * w};
                float4 b0 = *(const float4*)&Bsh[j * 132 + tx * 8];
                float4 b1 = *(const float4*)&Bsh[j * 132 + tx * 8 + 4];
                float b[8] = {b0.x, b0.y, b0.z, b0.w, b1.x, b1.y, b1.z, b1.w};
#pragma unroll
                for (int i = 0; i < 4; ++i)
#pragma unroll
                    for (int jn = 0; jn < 8; ++jn) acc[i][jn] += aw[i] * b[jn];
            }
        }
#pragma unroll
        for (int i = 0; i < 4; ++i) {
            size_t base = ((size_t)(c * Hh + h) * Pp + ty * 4 + i) * Nn + tx * 8;
            *(float4*)&d_st[base]     = make_float4(acc[i][0], acc[i][1], acc[i][2], acc[i][3]);
            *(float4*)&d_st[base + 4] = make_float4(acc[i][4], acc[i][5], acc[i][6], acc[i][7]);
        }
    }
}

// ---------------- inter-chunk scan (float2, writes fp16 prev) ----------------
__global__ void __launch_bounds__(256)
ssd_scan_k() {
    int idx2 = blockIdx.x * 256 + threadIdx.x;
    if (idx2 >= Hh * Pp * Nn / 2) return;
    int idx = idx2 * 2;
    int h = idx / (Pp * Nn);
    float2 carry = make_float2(0.f, 0.f);
#pragma unroll
    for (int c = 0; c < NC; ++c) {
        __half2 ph = __floats2half2_rn(carry.x, carry.y);
        *(__half2*)&d_prevh[(size_t)c * Hh * Pp * Nn + idx] = ph;
        float cdec = __expf(d_cum[(size_t)(c * CSz + CSz - 1) * Hh + h]);
        float2 st = *(const float2*)&d_st[(size_t)c * Hh * Pp * Nn + idx];
        carry.x = cdec * carry.x + st.x;
        carry.y = cdec * carry.y + st.y;
    }
}

// ---------------- inter-chunk output (fp16 MMA) + D*x ----------------
__global__ void __launch_bounds__(256)
ssd_inter_k(const float* __restrict__ Dp) {
    __shared__ __align__(16) __half Cs[64 * CW];
    __shared__ __align__(16) __half Ph[64 * CW];
    __shared__ float cum_i[64];

    const int it = blockIdx.x, h = blockIdx.y, c = blockIdx.z;
    const int g = h >> 4;
    const int tid = threadIdx.x;
    const int wid = tid >> 5, lane = tid & 31;
    const int gq = lane >> 2, q = lane & 3;
    const int mw = wid >> 1;
    const int nw = wid & 1;

    const int li0 = c * CSz + it * 64;
    const int ccol = INTERC + Gg * Nn + g * Nn;
    const size_t pbase = ((size_t)(c * Hh + h) * Pp) * Nn;

#pragma unroll
    for (int rep = 0; rep < 4; ++rep) {
        int idx = tid + rep * 256;
        int r = idx >> 4, qq = idx & 15;
        *(uint4*)&Cs[r * CW + qq * 8] =
            *(const uint4*)&d_xbch[(size_t)(li0 + r) * CONVC + ccol + qq * 8];
        *(uint4*)&Ph[r * CW + qq * 8] =
            *(const uint4*)&d_prevh[pbase + (size_t)r * Nn + qq * 8];
    }
    if (tid < 64) cum_i[tid] = d_cum[(size_t)(li0 + tid) * Hh + h];
    __syncthreads();

    const uint32_t CsB = smem_u32(Cs), PhB = smem_u32(Ph);
    const uint32_t a_off = (uint32_t)((mw * 16 + (lane & 15)) * CW + ((lane >> 4) & 1) * 8) * 2;
    const uint32_t b_off = (uint32_t)((nw * 32 + (lane & 7) + ((lane >> 4) & 1) * 8) * CW + ((lane >> 3) & 1) * 8) * 2;

    float acc[4][4];
#pragma unroll
    for (int i = 0; i < 4; ++i)
#pragma unroll
        for (int j = 0; j < 4; ++j) acc[i][j] = 0.f;

#pragma unroll
    for (int ks = 0; ks < 8; ++ks) {
        const uint32_t kadd = (uint32_t)ks * 32;
        uint32_t af[4];
        ldm_x4(af, CsB + a_off + kadd);
        uint32_t bf[2][4];
        ldm_x4(bf[0], PhB + b_off + kadd);
        ldm_x4(bf[1], PhB + b_off + (uint32_t)(16 * CW) * 2 + kadd);
#pragma unroll
        for (int ni = 0; ni < 4; ++ni)
            mma_f16(acc[ni], af, &bf[ni >> 1][(ni & 1) * 2]);
    }

    const int i0 = mw * 16 + gq;
    const float esc0 = __expf(cum_i[i0]);
    const float esc1 = __expf(cum_i[i0 + 8]);
    const float Dh = Dp[h];
#pragma unroll
    for (int ni = 0; ni < 4; ++ni) {
        int p = nw * 32 + ni * 8 + 2 * q;
        size_t y0 = (size_t)(li0 + i0) * INTERC + h * Pp + p;
        size_t y1 = (size_t)(li0 + i0 + 8) * INTERC + h * Pp + p;
        size_t x0 = (size_t)(li0 + i0) * CONVC + h * Pp + p;
        size_t x1 = (size_t)(li0 + i0 + 8) * CONVC + h * Pp + p;
        float2 yv0 = *(const float2*)&d_y[y0];
        float2 yv1 = *(const float2*)&d_y[y1];
        float2 xv0 = *(const float2*)&d_xbc[x0];
        float2 xv1 = *(const float2*)&d_xbc[x1];
        yv0.x += esc0 * acc[ni][0] + Dh * xv0.x;
        yv0.y += esc0 * acc[ni][1] + Dh * xv0.y;
        yv1.x += esc1 * acc[ni][2] + Dh * xv1.x;
        yv1.y += esc1 * acc[ni][3] + Dh * xv1.y;
        *(float2*)&d_y[y0] = yv0;
        *(float2*)&d_y[y1] = yv1;
    }
}

// ---------------- gated RMS group-norm (writes fp16 d_gh) ----------------
__global__ void __launch_bounds__(256)
gated_norm_k(const float* __restrict__ norm_w) {
    const int l = blockIdx.x, grp = blockIdx.y;
    const int tid = threadIdx.x;
    float v[4];
    float ss = 0.f;
#pragma unroll
    for (int i = 0; i < 4; ++i) {
        int col = grp * GSZ + tid + i * 256;
        float gate = d_proj[(size_t)l * PROJC + col];
        float yv = d_y[(size_t)l * INTERC + col];
        float sg = gate / (1.f + __expf(-gate));
        v[i] = yv * sg;
        ss += v[i] * v[i];
    }
#pragma unroll
    for (int off = 16; off; off >>= 1) ss += __shfl_xor_sync(0xffffffffu, ss, off);
    __shared__ float red[8];
    if ((tid & 31) == 0) red[tid >> 5] = ss;
    __syncthreads();
    float tot = red[0] + red[1] + red[2] + red[3] + red[4] + red[5] + red[6] + red[7];
    float rs = rsqrtf(tot / (float)GSZ + EPSf);
#pragma unroll
    for (int i = 0; i < 4; ++i) {
        int col = grp * GSZ + tid + i * 256;
        d_gh[(size_t)l * INTERC + col] = __float2half_rn(v[i] * rs * norm_w[col]);
    }
}

// ---------------- launch ----------------
extern "C" void kernel_launch(void* const* d_in, const int* in_sizes, int n_in,
                              void* d_out, int out_size) {
    const float* input     = (const float*)d_in[0];
    const float* in_proj_w = (const float*)d_in[1];
    const float* conv_w    = (const float*)d_in[2];
    const float* conv_b    = (const float*)d_in[3];
    const float* dt_bias   = (const float*)d_in[4];
    const float* A_log     = (const float*)d_in[5];
    const float* Dp        = (const float*)d_in[6];
    const float* norm_w    = (const float*)d_in[7];
    const float* out_w     = (const float*)d_in[8];
    float* out = (float*)d_out;

    cudaFuncSetAttribute(gemm1_mma_k, cudaFuncAttributeMaxDynamicSharedMemorySize, GM_SMEM);
    cudaFuncSetAttribute(gemm2_mma_k, cudaFuncAttributeMaxDynamicSharedMemorySize, GM_SMEM);
    cudaFuncSetAttribute(ssd_intra_states_k, cudaFuncAttributeMaxDynamicSharedMemorySize, IT_SMEM2);

    __half* ha;  cudaGetSymbolAddress((void**)&ha,  d_ha);
    __half* hb1; cudaGetSymbolAddress((void**)&hb1, d_hb1);
    __half* hb2; cudaGetSymbolAddress((void**)&hb2, d_hb2);

    // 0. merged fp16 pre-convert (grid-stride)
    cvt_all_k<<<4096, 256>>>((const float4*)input, (uint2*)ha,
                             (const float4*)in_proj_w, (uint2*)hb1,
                             (const float4*)out_w, (uint2*)hb2);

    // 1. in_proj GEMM (fp16 mma)
    gemm1_mma_k<<<dim3(Lq / BMt, PROJC / BNt), 256, GM_SMEM>>>();
    // 2. fused conv+SiLU (float4, f32+f16) || dt warp-scan
    conv_dt_k<<<dim3(11, Lq), 256>>>(conv_w, conv_b, dt_bias, A_log);
    // 3. fused intra-chunk (fp16 MMA) || chunk-states (fp32)
    ssd_intra_states_k<<<dim3(5, Hh, NC), 256, IT_SMEM2>>>();
    // 4. inter-chunk sequential scan -> d_prevh (fp16)
    ssd_scan_k<<<(Hh * Pp * Nn / 2 + 255) / 256, 256>>>();
    // 5. inter-chunk contribution (fp16 MMA) + D*x -> d_y (final)
    ssd_inter_k<<<dim3(4, Hh, NC), 256>>>(Dp);
    // 6. gated RMS group-norm -> d_gh (fp16)
    gated_norm_k<<<dim3(Lq, Gg), 256>>>(norm_w);
    // 7. out GEMM (fp16 mma)
    gemm2_mma_k<<<dim3(Lq / BMt, HIDm / BNt), 256, GM_SMEM>>>(out);
}

// round 14
// speedup vs baseline: 1.0669x; 1.0669x over previous
#include <cuda_runtime.h>
#include <cuda_fp16.h>
#include <math.h>
#include <stdint.h>

// ---------------- problem constants ----------------
#define Lq     2048
#define HIDm   4096
#define Hh     128
#define Pp     64
#define Nn     128
#define Gg     8
#define Kk     4
#define CSz    256
#define NC     8            // L / CS
#define INTERC 8192         // H*P
#define CONVC  10240        // INTER + 2*G*N
#define PROJC  18560        // INTER + CONV + H
#define GSZ    1024         // INTER / G
#define EPSf   1e-5f

// ---------------- scratch (static device globals; no allocation) ----------------
__device__ float d_proj[(size_t)Lq * PROJC];
__device__ float d_xbc [(size_t)Lq * CONVC];
__device__ float d_dt  [(size_t)Lq * Hh];
__device__ float d_cum [(size_t)Lq * Hh];
__device__ float d_y   [(size_t)Lq * INTERC];
__device__ float d_st  [(size_t)NC * Hh * Pp * Nn];
// fp16 operands
__device__ __align__(16) __half d_ha   [(size_t)Lq * HIDm];
__device__ __align__(16) __half d_hb1  [(size_t)PROJC * HIDm];
__device__ __align__(16) __half d_hb2  [(size_t)HIDm * INTERC];
__device__ __align__(16) __half d_gh   [(size_t)Lq * INTERC];
__device__ __align__(16) __half d_xbch [(size_t)Lq * CONVC];
__device__ __align__(16) __half d_prevh[(size_t)NC * Hh * Pp * Nn];

__device__ __forceinline__ uint32_t smem_u32(const void* p) {
    return (uint32_t)__cvta_generic_to_shared(p);
}
__device__ __forceinline__ void cp16(uint32_t dst, const void* src) {
    asm volatile("cp.async.cg.shared.global [%0], [%1], 16;\n" :: "r"(dst), "l"(src));
}
__device__ __forceinline__ void mma_f16(float* c, const uint32_t* a, const uint32_t* b) {
    asm volatile(
        "mma.sync.aligned.m16n8k16.row.col.f32.f16.f16.f32 "
        "{%0,%1,%2,%3}, {%4,%5,%6,%7}, {%8,%9}, {%0,%1,%2,%3};"
        : "+f"(c[0]), "+f"(c[1]), "+f"(c[2]), "+f"(c[3])
        : "r"(a[0]), "r"(a[1]), "r"(a[2]), "r"(a[3]), "r"(b[0]), "r"(b[1]));
}
__device__ __forceinline__ void ldm_x4(uint32_t* r, uint32_t addr) {
    asm volatile("ldmatrix.sync.aligned.m8n8.x4.shared.b16 {%0,%1,%2,%3}, [%4];"
                 : "=r"(r[0]), "=r"(r[1]), "=r"(r[2]), "=r"(r[3]) : "r"(addr));
}

// ---------------- merged fp32 -> fp16 pre-convert (grid-stride, 3 segments) ----------------
#define N4_A  (Lq * HIDm / 4)
#define N4_B1 (PROJC * HIDm / 4)
#define N4_B2 (HIDm * INTERC / 4)
__global__ void __launch_bounds__(256)
cvt_all_k(const float4* __restrict__ inA, uint2* __restrict__ outA,
          const float4* __restrict__ inB1, uint2* __restrict__ outB1,
          const float4* __restrict__ inB2, uint2* __restrict__ outB2) {
    const int total = N4_A + N4_B1 + N4_B2;
    for (int i = blockIdx.x * 256 + threadIdx.x; i < total; i += gridDim.x * 256) {
        const float4* src;
        uint2* dst;
        int idx;
        if (i < N4_A)            { src = inA;  dst = outA;  idx = i; }
        else if (i < N4_A + N4_B1) { src = inB1; dst = outB1; idx = i - N4_A; }
        else                     { src = inB2; dst = outB2; idx = i - N4_A - N4_B1; }
        float4 v = src[idx];
        __half2 lo = __floats2half2_rn(v.x, v.y);
        __half2 hi = __floats2half2_rn(v.z, v.w);
        uint2 o;
        o.x = *(const uint32_t*)&lo;
        o.y = *(const uint32_t*)&hi;
        dst[idx] = o;
    }
}

// =====================================================================
//  fp16 mma GEMM (R7 config, frozen)
// =====================================================================
#define BMt 128
#define BNt 128
#define BKh 64
#define PADh 72
#define STAGE_H ((BMt + BNt) * PADh)
#define GM_SMEM (3 * STAGE_H * 2)

__device__ __forceinline__ void gemm_f16_body(const __half* __restrict__ A,
                                              const __half* __restrict__ B,
                                              float* __restrict__ C,
                                              int Ncols, int K) {
    extern __shared__ __half smh[];
    const uint32_t sbase = smem_u32(smh);
    const int tid = threadIdx.x, wid = tid >> 5, lane = tid & 31;
    const int g = lane >> 2, q = lane & 3;
    const int m0 = blockIdx.x * BMt;
    const int n0 = blockIdx.y * BNt;
    const int wm = (wid >> 1) * 32;
    const int wn = (wid & 1) * 64;
    const int nk = K / BKh;

    const int a_row = wm + (lane & 15);
    const int a_kh  = ((lane >> 4) & 1) * 8;
    const uint32_t a_off = (uint32_t)(a_row * PADh + a_kh) * 2;
    const int b_nrow = (lane & 7) + ((lane >> 4) & 1) * 8;
    const int b_kh   = ((lane >> 3) & 1) * 8;
    const uint32_t b_off = (uint32_t)(BMt * PADh + (wn + b_nrow) * PADh + b_kh) * 2;

    float acc[2][8][4];
#pragma unroll
    for (int i = 0; i < 2; ++i)
#pragma unroll
        for (int j = 0; j < 8; ++j)
#pragma unroll
            for (int r = 0; r < 4; ++r) acc[i][j][r] = 0.f;

    auto load_stage = [&](int c) {
        const int s = c % 3;
        const int k0 = c * BKh;
        const uint32_t abase = sbase + s * STAGE_H * 2;
        const uint32_t bbase = abase + BMt * PADh * 2;
#pragma unroll
        for (int i = 0; i < 4; ++i) {
            int t = tid + i * 256;
            int r = t >> 3, qq = t & 7;
            cp16(abase + (uint32_t)(r * PADh + qq * 8) * 2,
                 A + (size_t)(m0 + r) * K + k0 + qq * 8);
        }
#pragma unroll
        for (int i = 0; i < 4; ++i) {
            int t = tid + i * 256;
            int r = t >> 3, qq = t & 7;
            cp16(bbase + (uint32_t)(r * PADh + qq * 8) * 2,
                 B + (size_t)(n0 + r) * K + k0 + qq * 8);
        }
        asm volatile("cp.async.commit_group;");
    };

    load_stage(0);
    load_stage(1);

    for (int c = 0; c < nk; ++c) {
        if (c + 1 < nk) {
            asm volatile("cp.async.wait_group 1;");
        } else {
            asm volatile("cp.async.wait_group 0;");
        }
        __syncthreads();

        if (c + 2 < nk) load_stage(c + 2);

        const uint32_t stg = sbase + (uint32_t)(c % 3) * STAGE_H * 2;
        const uint32_t a_addr = stg + a_off;
        const uint32_t b_addr = stg + b_off;

#pragma unroll
        for (int ks = 0; ks < 4; ++ks) {
            const uint32_t kadd = (uint32_t)ks * 32;
            uint32_t af[2][4];
            ldm_x4(af[0], a_addr + kadd);
            ldm_x4(af[1], a_addr + 16 * PADh * 2 + kadd);
            uint32_t bf[4][4];
#pragma unroll
            for (int nb = 0; nb < 4; ++nb)
                ldm_x4(bf[nb], b_addr + (uint32_t)(nb * 16 * PADh) * 2 + kadd);
#pragma unroll
            for (int mi = 0; mi < 2; ++mi)
#pragma unroll
                for (int ni = 0; ni < 8; ++ni)
                    mma_f16(acc[mi][ni], af[mi], &bf[ni >> 1][(ni & 1) * 2]);
        }
    }

#pragma unroll
    for (int mi = 0; mi < 2; ++mi) {
        const int r = m0 + wm + mi * 16 + g;
#pragma unroll
        for (int ni = 0; ni < 8; ++ni) {
            const int cb = n0 + wn + ni * 8 + 2 * q;
            *(float2*)(C + (size_t)r * Ncols + cb) =
                make_float2(acc[mi][ni][0], acc[mi][ni][1]);
            *(float2*)(C + (size_t)(r + 8) * Ncols + cb) =
                make_float2(acc[mi][ni][2], acc[mi][ni][3]);
        }
    }
}

__global__ void __launch_bounds__(256, 2)
gemm1_mma_k() { gemm_f16_body(d_ha, d_hb1, d_proj, PROJC, HIDm); }
__global__ void __launch_bounds__(256, 2)
gemm2_mma_k(float* __restrict__ C) { gemm_f16_body(d_gh, d_hb2, C, HIDm, INTERC); }

// ---------------- fused: conv+SiLU (float4, f32 + f16 mirror) || dt warp-scan ----------------
__global__ void __launch_bounds__(256)
conv_dt_k(const float* __restrict__ w, const float* __restrict__ b,
          const float* __restrict__ dt_bias, const float* __restrict__ A_log) {
    if (blockIdx.x < 10) {
        int c = (blockIdx.x * 256 + threadIdx.x) * 4;
        int l = blockIdx.y;
        float4 w0 = *(const float4*)&w[(c + 0) * 4];
        float4 w1 = *(const float4*)&w[(c + 1) * 4];
        float4 w2 = *(const float4*)&w[(c + 2) * 4];
        float4 w3 = *(const float4*)&w[(c + 3) * 4];
        float4 acc = *(const float4*)&b[c];
#pragma unroll
        for (int k = 0; k < Kk; ++k) {
            int ls = l - (Kk - 1) + k;
            if (ls >= 0) {
                float4 pv = *(const float4*)&d_proj[(size_t)ls * PROJC + INTERC + c];
                acc.x += ((const float*)&w0)[k] * pv.x;
                acc.y += ((const float*)&w1)[k] * pv.y;
                acc.z += ((const float*)&w2)[k] * pv.z;
                acc.w += ((const float*)&w3)[k] * pv.w;
            }
        }
        acc.x = acc.x / (1.f + __expf(-acc.x));
        acc.y = acc.y / (1.f + __expf(-acc.y));
        acc.z = acc.z / (1.f + __expf(-acc.z));
        acc.w = acc.w / (1.f + __expf(-acc.w));
        *(float4*)&d_xbc[(size_t)l * CONVC + c] = acc;
        __half2 lo = __floats2half2_rn(acc.x, acc.y);
        __half2 hi = __floats2half2_rn(acc.z, acc.w);
        uint2 o;
        o.x = *(const uint32_t*)&lo;
        o.y = *(const uint32_t*)&hi;
        *(uint2*)&d_xbch[(size_t)l * CONVC + c] = o;
    } else {
        if (blockIdx.y >= 1024) return;
        int h = blockIdx.y & 127, c = blockIdx.y >> 7, t = threadIdx.x;
        int lane = t & 31, warp = t >> 5;
        int l = c * CSz + t;
        float x = d_proj[(size_t)l * PROJC + (INTERC + CONVC) + h] + dt_bias[h];
        float sp = fmaxf(x, 0.f) + log1pf(expf(-fabsf(x)));
        float dtv = fmaxf(sp, 0.f);
        float A = -expf(A_log[h]);
        float val = dtv * A;
#pragma unroll
        for (int o = 1; o < 32; o <<= 1) {
            float n = __shfl_up_sync(0xffffffffu, val, o);
            if (lane >= o) val += n;
        }
        __shared__ float wsum[8];
        if (lane == 31) wsum[warp] = val;
        __syncthreads();
        if (warp == 0 && lane < 8) {
            float v = wsum[lane];
#pragma unroll
            for (int o = 1; o < 8; o <<= 1) {
                float n = __shfl_up_sync(0xffu, v, o);
                if (lane >= o) v += n;
            }
            wsum[lane] = v;
        }
        __syncthreads();
        float base = (warp > 0) ? wsum[warp - 1] : 0.f;
        d_dt [(size_t)l * Hh + h] = dtv;
        d_cum[(size_t)l * Hh + h] = val + base;
    }
}

// ---------------- fused: intra-chunk (fp16 MMA) || chunk-states (fp16 MMA) ----------------
#define CW 136
#define SW 72
#define IT_HALVES (64 * (2 * CW + 3 * SW))
#define IT_SMEM2  (IT_HALVES * 2 + 3 * 64 * 4)     // 63232 B
__global__ void __launch_bounds__(256, 2)
ssd_intra_states_k() {
    extern __shared__ __align__(16) char sraw[];
    const int h = blockIdx.y, c = blockIdx.z;
    const int g = h >> 4;
    const int tid = threadIdx.x;
    const int wid = tid >> 5, lane = tid & 31;
    const int gq = lane >> 2, q = lane & 3;
    const int mw = wid >> 1;
    const int nw = wid & 1;

    if (blockIdx.x < 4) {
        // ================= intra branch: fp16 tensor-core =================
        __half* Cs  = (__half*)sraw;
        __half* Bs  = Cs + 64 * CW;
        __half* Ss  = Bs + 64 * CW;
        __half* Xs  = Ss + 64 * SW;
        __half* XsT = Xs + 64 * SW;
        float* cum_i = (float*)(XsT + 64 * SW);
        float* cum_j = cum_i + 64;
        float* dtj   = cum_j + 64;

        const int it = blockIdx.x;
        const int li0 = c * CSz + it * 64;
        const int ccol = INTERC + Gg * Nn + g * Nn;
        const int bcol = INTERC + g * Nn;

        const uint32_t CsB = smem_u32(Cs), BsB = smem_u32(Bs);
        const uint32_t SsB = smem_u32(Ss), XtB = smem_u32(XsT);
        const uint32_t aS_off = (uint32_t)((mw * 16 + (lane & 15)) * CW + ((lane >> 4) & 1) * 8) * 2;
        const uint32_t bS_off = (uint32_t)((nw * 32 + (lane & 7) + ((lane >> 4) & 1) * 8) * CW + ((lane >> 3) & 1) * 8) * 2;
        const uint32_t aY_off = (uint32_t)((mw * 16 + (lane & 15)) * SW + ((lane >> 4) & 1) * 8) * 2;
        const uint32_t bY_off = (uint32_t)((nw * 32 + (lane & 7) + ((lane >> 4) & 1) * 8) * SW + ((lane >> 3) & 1) * 8) * 2;

#pragma unroll
        for (int rep = 0; rep < 4; ++rep) {
            int idx = tid + rep * 256;
            int r = idx >> 4, qq = idx & 15;
            *(uint4*)&Cs[r * CW + qq * 8] =
                *(const uint4*)&d_xbch[(size_t)(li0 + r) * CONVC + ccol + qq * 8];
        }
        if (tid < 64) cum_i[tid] = d_cum[(size_t)(li0 + tid) * Hh + h];

        float accY[4][4];
#pragma unroll
        for (int i = 0; i < 4; ++i)
#pragma unroll
            for (int j = 0; j < 4; ++j) accY[i][j] = 0.f;

        const int i0 = mw * 16 + gq;

        for (int jt = 0; jt <= it; ++jt) {
            const int lj0 = c * CSz + jt * 64;
            __syncthreads();
#pragma unroll
            for (int rep = 0; rep < 4; ++rep) {
                int idx = tid + rep * 256;
                int r = idx >> 4, qq = idx & 15;
                *(uint4*)&Bs[r * CW + qq * 8] =
                    *(const uint4*)&d_xbch[(size_t)(lj0 + r) * CONVC + bcol + qq * 8];
            }
#pragma unroll
            for (int rep = 0; rep < 2; ++rep) {
                int idx = tid + rep * 256;
                int r = idx >> 3, qq = idx & 7;
                *(uint4*)&Xs[r * SW + qq * 8] =
                    *(const uint4*)&d_xbch[(size_t)(lj0 + r) * CONVC + h * Pp + qq * 8];
            }
            if (tid < 64) {
                cum_j[tid] = d_cum[(size_t)(lj0 + tid) * Hh + h];
                dtj  [tid] = d_dt [(size_t)(lj0 + tid) * Hh + h];
            }
            __syncthreads();

#pragma unroll
            for (int rep = 0; rep < 4; ++rep) {
                int idx = tid + rep * 256;
                int bb = idx >> 5, aa = idx & 31;
                uint32_t u0 = *(uint32_t*)&Xs[(2 * bb) * SW + 2 * aa];
                uint32_t u1 = *(uint32_t*)&Xs[(2 * bb + 1) * SW + 2 * aa];
                uint32_t lo = (u0 & 0xffffu) | (u1 << 16);
                uint32_t hi = (u0 >> 16) | (u1 & 0xffff0000u);
                *(uint32_t*)&XsT[(2 * aa) * SW + 2 * bb] = lo;
                *(uint32_t*)&XsT[(2 * aa + 1) * SW + 2 * bb] = hi;
            }

            float accS[4][4];
#pragma unroll
            for (int i = 0; i < 4; ++i)
#pragma unroll
                for (int j = 0; j < 4; ++j) accS[i][j] = 0.f;
#pragma unroll
            for (int ks = 0; ks < 8; ++ks) {
                const uint32_t kadd = (uint32_t)ks * 32;
                uint32_t af[4];
                ldm_x4(af, CsB + aS_off + kadd);
                uint32_t bf[2][4];
                ldm_x4(bf[0], BsB + bS_off + kadd);
                ldm_x4(bf[1], BsB + bS_off + (uint32_t)(16 * CW) * 2 + kadd);
#pragma unroll
                for (int ni = 0; ni < 4; ++ni)
                    mma_f16(accS[ni], af, &bf[ni >> 1][(ni & 1) * 2]);
            }

            {
                const float ci0 = cum_i[i0], ci1 = cum_i[i0 + 8];
                const int gi0 = it * 64 + i0, gi1 = gi0 + 8;
#pragma unroll
                for (int ni = 0; ni < 4; ++ni) {
                    int jb = nw * 32 + ni * 8 + 2 * q;
                    float cj0 = cum_j[jb], cj1 = cum_j[jb + 1];
                    float dj0 = dtj[jb],  dj1 = dtj[jb + 1];
                    int gj0 = jt * 64 + jb, gj1 = gj0 + 1;
                    float v00 = (gi0 >= gj0) ? accS[ni][0] * __expf(ci0 - cj0) * dj0 : 0.f;
                    float v01 = (gi0 >= gj1) ? accS[ni][1] * __expf(ci0 - cj1) * dj1 : 0.f;
                    float v10 = (gi1 >= gj0) ? accS[ni][2] * __expf(ci1 - cj0) * dj0 : 0.f;
                    float v11 = (gi1 >= gj1) ? accS[ni][3] * __expf(ci1 - cj1) * dj1 : 0.f;
                    __half2 h0 = __floats2half2_rn(v00, v01);
                    __half2 h1 = __floats2half2_rn(v10, v11);
                    *(__half2*)&Ss[i0 * SW + jb] = h0;
                    *(__half2*)&Ss[(i0 + 8) * SW + jb] = h1;
                }
            }
            __syncthreads();

#pragma unroll
            for (int ks = 0; ks < 4; ++ks) {
                const uint32_t kadd = (uint32_t)ks * 32;
                uint32_t af[4];
                ldm_x4(af, SsB + aY_off + kadd);
                uint32_t bf[2][4];
                ldm_x4(bf[0], XtB + bY_off + kadd);
                ldm_x4(bf[1], XtB + bY_off + (uint32_t)(16 * SW) * 2 + kadd);
#pragma unroll
                for (int ni = 0; ni < 4; ++ni)
                    mma_f16(accY[ni], af, &bf[ni >> 1][(ni & 1) * 2]);
            }
        }

#pragma unroll
        for (int ni = 0; ni < 4; ++ni) {
            int p = nw * 32 + ni * 8 + 2 * q;
            *(float2*)&d_y[(size_t)(li0 + i0) * INTERC + h * Pp + p] =
                make_float2(accY[ni][0], accY[ni][1]);
            *(float2*)&d_y[(size_t)(li0 + i0 + 8) * INTERC + h * Pp + p] =
                make_float2(accY[ni][2], accY[ni][3]);
        }
    } else {
        // ============== states branch: fp16 tensor-core ==============
        // st[p][n] = sum_j (w_j * x[j][p]) * B[j][n]; A=WXT[p][j], Bop=BT[n][j]
        float*  Xsf = (float*)sraw;                 // [64 j][68 p] fp32
        __half* WXT = (__half*)(Xsf + 64 * 68);     // [64 p][72 j]
        __half* Bs2 = WXT + 64 * SW;                // [64 j][136 n]
        __half* BT  = Bs2 + 64 * CW;                // [128 n][72 j]
        float*  ws  = (float*)(BT + 128 * SW);      // [64]

        const uint32_t WxB = smem_u32(WXT), BtB = smem_u32(BT);
        const uint32_t aT_off = (uint32_t)((mw * 16 + (lane & 15)) * SW + ((lane >> 4) & 1) * 8) * 2;
        const uint32_t bT_off = (uint32_t)((nw * 64 + (lane & 7) + ((lane >> 4) & 1) * 8) * SW + ((lane >> 3) & 1) * 8) * 2;

        const float cum_last = d_cum[(size_t)(c * CSz + CSz - 1) * Hh + h];

        float acc[8][4];
#pragma unroll
        for (int i = 0; i < 8; ++i)
#pragma unroll
            for (int j = 0; j < 4; ++j) acc[i][j] = 0.f;

        for (int j0 = 0; j0 < CSz; j0 += 64) {
            __syncthreads();
            // stage X fp32 (64j x 64p) + B fp16 (64j x 128n) + ws
#pragma unroll
            for (int rep = 0; rep < 4; ++rep) {
                int idx = tid + rep * 256;
                int r = idx >> 4, qn = idx & 15;
                *(float4*)&Xsf[r * 68 + qn * 4] =
                    *(const float4*)&d_xbc[(size_t)(c * CSz + j0 + r) * CONVC + h * Pp + qn * 4];
            }
#pragma unroll
            for (int rep = 0; rep < 4; ++rep) {
                int idx = tid + rep * 256;
                int r = idx >> 4, qq = idx & 15;
                *(uint4*)&Bs2[r * CW + qq * 8] =
                    *(const uint4*)&d_xbch[(size_t)(c * CSz + j0 + r) * CONVC + INTERC + g * Nn + qq * 8];
            }
            if (tid < 64) {
                int l = c * CSz + j0 + tid;
                ws[tid] = d_dt[(size_t)l * Hh + h] * __expf(cum_last - d_cum[(size_t)l * Hh + h]);
            }
            __syncthreads();

            // WXT[p][j] = w_j * x[j][p]  (2x2 blocks, single fp16 rounding)
#pragma unroll
            for (int rep = 0; rep < 4; ++rep) {
                int idx = tid + rep * 256;
                int jb = idx >> 5, pb = idx & 31;
                float2 a0 = *(const float2*)&Xsf[(2 * jb) * 68 + 2 * pb];
                float2 a1 = *(const float2*)&Xsf[(2 * jb + 1) * 68 + 2 * pb];
                float w0 = ws[2 * jb], w1 = ws[2 * jb + 1];
                *(__half2*)&WXT[(2 * pb) * SW + 2 * jb]     = __floats2half2_rn(w0 * a0.x, w1 * a1.x);
                *(__half2*)&WXT[(2 * pb + 1) * SW + 2 * jb] = __floats2half2_rn(w0 * a0.y, w1 * a1.y);
            }
            // BT[n][j] = B[j][n] transpose (2x2 half blocks)
#pragma unroll
            for (int rep = 0; rep < 8; ++rep) {
                int idx = tid + rep * 256;
                int jb = idx >> 6, nb2 = idx & 63;
                uint32_t u0 = *(uint32_t*)&Bs2[(2 * jb) * CW + 2 * nb2];
                uint32_t u1 = *(uint32_t*)&Bs2[(2 * jb + 1) * CW + 2 * nb2];
                uint32_t lo = (u0 & 0xffffu) | (u1 << 16);
                uint32_t hi = (u0 >> 16) | (u1 & 0xffff0000u);
                *(uint32_t*)&BT[(2 * nb2) * SW + 2 * jb] = lo;
                *(uint32_t*)&BT[(2 * nb2 + 1) * SW + 2 * jb] = hi;
            }
            __syncthreads();

            // MMA: 4 k16 steps over this 64-j block
#pragma unroll
            for (int ks = 0; ks < 4; ++ks) {
                const uint32_t kadd = (uint32_t)ks * 32;
                uint32_t af[4];
                ldm_x4(af, WxB + aT_off + kadd);
                uint32_t bf[4][4];
#pragma unroll
                for (int nb = 0; nb < 4; ++nb)
                    ldm_x4(bf[nb], BtB + bT_off + (uint32_t)(nb * 16 * SW) * 2 + kadd);
#pragma unroll
                for (int ni = 0; ni < 8; ++ni)
                    mma_f16(acc[ni], af, &bf[ni >> 1][(ni & 1) * 2]);
            }
        }

        // epilogue: st[p][n] fp32
        const int p0 = mw * 16 + gq;
#pragma unroll
        for (int ni = 0; ni < 8; ++ni) {
            int nn = nw * 64 + ni * 8 + 2 * q;
            size_t b0 = ((size_t)(c * Hh + h) * Pp + p0) * Nn + nn;
            size_t b1 = ((size_t)(c * Hh + h) * Pp + p0 + 8) * Nn + nn;
            *(float2*)&d_st[b0] = make_float2(acc[ni][0], acc[ni][1]);
            *(float2*)&d_st[b1] = make_float2(acc[ni][2], acc[ni][3]);
        }
    }
}

// ---------------- inter-chunk scan (float2, writes fp16 prev) ----------------
__global__ void __launch_bounds__(256)
ssd_scan_k() {
    int idx2 = blockIdx.x * 256 + threadIdx.x;
    if (idx2 >= Hh * Pp * Nn / 2) return;
    int idx = idx2 * 2;
    int h = idx / (Pp * Nn);
    float2 carry = make_float2(0.f, 0.f);
#pragma unroll
    for (int c = 0; c < NC; ++c) {
        __half2 ph = __floats2half2_rn(carry.x, carry.y);
        *(__half2*)&d_prevh[(size_t)c * Hh * Pp * Nn + idx] = ph;
        float cdec = __expf(d_cum[(size_t)(c * CSz + CSz - 1) * Hh + h]);
        float2 st = *(const float2*)&d_st[(size_t)c * Hh * Pp * Nn + idx];
        carry.x = cdec * carry.x + st.x;
        carry.y = cdec * carry.y + st.y;
    }
}

// ---------------- inter-chunk output (fp16 MMA) + D*x ----------------
__global__ void __launch_bounds__(256)
ssd_inter_k(const float* __restrict__ Dp) {
    __shared__ __align__(16) __half Cs[64 * CW];
    __shared__ __align__(16) __half Ph[64 * CW];
    __shared__ float cum_i[64];

    const int it = blockIdx.x, h = blockIdx.y, c = blockIdx.z;
    const int g = h >> 4;
    const int tid = threadIdx.x;
    const int wid = tid >> 5, lane = tid & 31;
    const int gq = lane >> 2, q = lane & 3;
    const int mw = wid >> 1;
    const int nw = wid & 1;

    const int li0 = c * CSz + it * 64;
    const int ccol = INTERC + Gg * Nn + g * Nn;
    const size_t pbase = ((size_t)(c * Hh + h) * Pp) * Nn;

#pragma unroll
    for (int rep = 0; rep < 4; ++rep) {
        int idx = tid + rep * 256;
        int r = idx >> 4, qq = idx & 15;
        *(uint4*)&Cs[r * CW + qq * 8] =
            *(const uint4*)&d_xbch[(size_t)(li0 + r) * CONVC + ccol + qq * 8];
        *(uint4*)&Ph[r * CW + qq * 8] =
            *(const uint4*)&d_prevh[pbase + (size_t)r * Nn + qq * 8];
    }
    if (tid < 64) cum_i[tid] = d_cum[(size_t)(li0 + tid) * Hh + h];
    __syncthreads();

    const uint32_t CsB = smem_u32(Cs), PhB = smem_u32(Ph);
    const uint32_t a_off = (uint32_t)((mw * 16 + (lane & 15)) * CW + ((lane >> 4) & 1) * 8) * 2;
    const uint32_t b_off = (uint32_t)((nw * 32 + (lane & 7) + ((lane >> 4) & 1) * 8) * CW + ((lane >> 3) & 1) * 8) * 2;

    float acc[4][4];
#pragma unroll
    for (int i = 0; i < 4; ++i)
#pragma unroll
        for (int j = 0; j < 4; ++j) acc[i][j] = 0.f;

#pragma unroll
    for (int ks = 0; ks < 8; ++ks) {
        const uint32_t kadd = (uint32_t)ks * 32;
        uint32_t af[4];
        ldm_x4(af, CsB + a_off + kadd);
        uint32_t bf[2][4];
        ldm_x4(bf[0], PhB + b_off + kadd);
        ldm_x4(bf[1], PhB + b_off + (uint32_t)(16 * CW) * 2 + kadd);
#pragma unroll
        for (int ni = 0; ni < 4; ++ni)
            mma_f16(acc[ni], af, &bf[ni >> 1][(ni & 1) * 2]);
    }

    const int i0 = mw * 16 + gq;
    const float esc0 = __expf(cum_i[i0]);
    const float esc1 = __expf(cum_i[i0 + 8]);
    const float Dh = Dp[h];
#pragma unroll
    for (int ni = 0; ni < 4; ++ni) {
        int p = nw * 32 + ni * 8 + 2 * q;
        size_t y0 = (size_t)(li0 + i0) * INTERC + h * Pp + p;
        size_t y1 = (size_t)(li0 + i0 + 8) * INTERC + h * Pp + p;
        size_t x0 = (size_t)(li0 + i0) * CONVC + h * Pp + p;
        size_t x1 = (size_t)(li0 + i0 + 8) * CONVC + h * Pp + p;
        float2 yv0 = *(const float2*)&d_y[y0];
        float2 yv1 = *(const float2*)&d_y[y1];
        float2 xv0 = *(const float2*)&d_xbc[x0];
        float2 xv1 = *(const float2*)&d_xbc[x1];
        yv0.x += esc0 * acc[ni][0] + Dh * xv0.x;
        yv0.y += esc0 * acc[ni][1] + Dh * xv0.y;
        yv1.x += esc1 * acc[ni][2] + Dh * xv1.x;
        yv1.y += esc1 * acc[ni][3] + Dh * xv1.y;
        *(float2*)&d_y[y0] = yv0;
        *(float2*)&d_y[y1] = yv1;
    }
}

// ---------------- gated RMS group-norm (writes fp16 d_gh) ----------------
__global__ void __launch_bounds__(256)
gated_norm_k(const float* __restrict__ norm_w) {
    const int l = blockIdx.x, grp = blockIdx.y;
    const int tid = threadIdx.x;
    float v[4];
    float ss = 0.f;
#pragma unroll
    for (int i = 0; i < 4; ++i) {
        int col = grp * GSZ + tid + i * 256;
        float gate = d_proj[(size_t)l * PROJC + col];
        float yv = d_y[(size_t)l * INTERC + col];
        float sg = gate / (1.f + __expf(-gate));
        v[i] = yv * sg;
        ss += v[i] * v[i];
    }
#pragma unroll
    for (int off = 16; off; off >>= 1) ss += __shfl_xor_sync(0xffffffffu, ss, off);
    __shared__ float red[8];
    if ((tid & 31) == 0) red[tid >> 5] = ss;
    __syncthreads();
    float tot = red[0] + red[1] + red[2] + red[3] + red[4] + red[5] + red[6] + red[7];
    float rs = rsqrtf(tot / (float)GSZ + EPSf);
#pragma unroll
    for (int i = 0; i < 4; ++i) {
        int col = grp * GSZ + tid + i * 256;
        d_gh[(size_t)l * INTERC + col] = __float2half_rn(v[i] * rs * norm_w[col]);
    }
}

// ---------------- launch ----------------
extern "C" void kernel_launch(void* const* d_in, const int* in_sizes, int n_in,
                              void* d_out, int out_size) {
    const float* input     = (const float*)d_in[0];
    const float* in_proj_w = (const float*)d_in[1];
    const float* conv_w    = (const float*)d_in[2];
    const float* conv_b    = (const float*)d_in[3];
    const float* dt_bias   = (const float*)d_in[4];
    const float* A_log     = (const float*)d_in[5];
    const float* Dp        = (const float*)d_in[6];
    const float* norm_w    = (const float*)d_in[7];
    const float* out_w     = (const float*)d_in[8];
    float* out = (float*)d_out;

    cudaFuncSetAttribute(gemm1_mma_k, cudaFuncAttributeMaxDynamicSharedMemorySize, GM_SMEM);
    cudaFuncSetAttribute(gemm2_mma_k, cudaFuncAttributeMaxDynamicSharedMemorySize, GM_SMEM);
    cudaFuncSetAttribute(ssd_intra_states_k, cudaFuncAttributeMaxDynamicSharedMemorySize, IT_SMEM2);

    __half* ha;  cudaGetSymbolAddress((void**)&ha,  d_ha);
    __half* hb1; cudaGetSymbolAddress((void**)&hb1, d_hb1);
    __half* hb2; cudaGetSymbolAddress((void**)&hb2, d_hb2);

    // 0. merged fp16 pre-convert (grid-stride)
    cvt_all_k<<<4096, 256>>>((const float4*)input, (uint2*)ha,
                             (const float4*)in_proj_w, (uint2*)hb1,
                             (const float4*)out_w, (uint2*)hb2);

    // 1. in_proj GEMM (fp16 mma)
    gemm1_mma_k<<<dim3(Lq / BMt, PROJC / BNt), 256, GM_SMEM>>>();
    // 2. fused conv+SiLU (float4, f32+f16) || dt warp-scan
    conv_dt_k<<<dim3(11, Lq), 256>>>(conv_w, conv_b, dt_bias, A_log);
    // 3. fused intra-chunk (fp16 MMA) || chunk-states (fp16 MMA)
    ssd_intra_states_k<<<dim3(5, Hh, NC), 256, IT_SMEM2>>>();
    // 4. inter-chunk sequential scan -> d_prevh (fp16)
    ssd_scan_k<<<(Hh * Pp * Nn / 2 + 255) / 256, 256>>>();
    // 5. inter-chunk contribution (fp16 MMA) + D*x -> d_y (final)
    ssd_inter_k<<<dim3(4, Hh, NC), 256>>>(Dp);
    // 6. gated RMS group-norm -> d_gh (fp16)
    gated_norm_k<<<dim3(Lq, Gg), 256>>>(norm_w);
    // 7. out GEMM (fp16 mma)
    gemm2_mma_k<<<dim3(Lq / BMt, HIDm / BNt), 256, GM_SMEM>>>(out);
}

// round 15
// speedup vs baseline: 1.0969x; 1.0281x over previous
#include <cuda_runtime.h>
#include <cuda_fp16.h>
#include <math.h>
#include <stdint.h>

// ---------------- problem constants ----------------
#define Lq     2048
#define HIDm   4096
#define Hh     128
#define Pp     64
#define Nn     128
#define Gg     8
#define Kk     4
#define CSz    256
#define NC     8            // L / CS
#define INTERC 8192         // H*P
#define CONVC  10240        // INTER + 2*G*N
#define PROJC  18560        // INTER + CONV + H
#define GSZ    1024         // INTER / G
#define EPSf   1e-5f

// ---------------- scratch (static device globals; no allocation) ----------------
__device__ float d_proj[(size_t)Lq * PROJC];
__device__ float d_xbc [(size_t)Lq * CONVC];
__device__ float d_dt  [(size_t)Lq * Hh];
__device__ float d_cum [(size_t)Lq * Hh];
__device__ float d_y   [(size_t)Lq * INTERC];
__device__ float d_st  [(size_t)NC * Hh * Pp * Nn];
// fp16 operands
__device__ __align__(16) __half d_ha   [(size_t)Lq * HIDm];
__device__ __align__(16) __half d_hb1  [(size_t)PROJC * HIDm];
__device__ __align__(16) __half d_hb2  [(size_t)HIDm * INTERC];
__device__ __align__(16) __half d_gh   [(size_t)Lq * INTERC];
__device__ __align__(16) __half d_xbch [(size_t)Lq * CONVC];
__device__ __align__(16) __half d_prevh[(size_t)NC * Hh * Pp * Nn];

__device__ __forceinline__ uint32_t smem_u32(const void* p) {
    return (uint32_t)__cvta_generic_to_shared(p);
}
__device__ __forceinline__ void cp16(uint32_t dst, const void* src) {
    asm volatile("cp.async.cg.shared.global [%0], [%1], 16;\n" :: "r"(dst), "l"(src));
}
__device__ __forceinline__ void mma_f16(float* c, const uint32_t* a, const uint32_t* b) {
    asm volatile(
        "mma.sync.aligned.m16n8k16.row.col.f32.f16.f16.f32 "
        "{%0,%1,%2,%3}, {%4,%5,%6,%7}, {%8,%9}, {%0,%1,%2,%3};"
        : "+f"(c[0]), "+f"(c[1]), "+f"(c[2]), "+f"(c[3])
        : "r"(a[0]), "r"(a[1]), "r"(a[2]), "r"(a[3]), "r"(b[0]), "r"(b[1]));
}
__device__ __forceinline__ void ldm_x4(uint32_t* r, uint32_t addr) {
    asm volatile("ldmatrix.sync.aligned.m8n8.x4.shared.b16 {%0,%1,%2,%3}, [%4];"
                 : "=r"(r[0]), "=r"(r[1]), "=r"(r[2]), "=r"(r[3]) : "r"(addr));
}

// ---------------- merged fp32 -> fp16 pre-convert (grid-stride, 3 segments) ----------------
#define N4_A  (Lq * HIDm / 4)
#define N4_B1 (PROJC * HIDm / 4)
#define N4_B2 (HIDm * INTERC / 4)
__global__ void __launch_bounds__(256)
cvt_all_k(const float4* __restrict__ inA, uint2* __restrict__ outA,
          const float4* __restrict__ inB1, uint2* __restrict__ outB1,
          const float4* __restrict__ inB2, uint2* __restrict__ outB2) {
    const int total = N4_A + N4_B1 + N4_B2;
    for (int i = blockIdx.x * 256 + threadIdx.x; i < total; i += gridDim.x * 256) {
        const float4* src;
        uint2* dst;
        int idx;
        if (i < N4_A)            { src = inA;  dst = outA;  idx = i; }
        else if (i < N4_A + N4_B1) { src = inB1; dst = outB1; idx = i - N4_A; }
        else                     { src = inB2; dst = outB2; idx = i - N4_A - N4_B1; }
        float4 v = src[idx];
        __half2 lo = __floats2half2_rn(v.x, v.y);
        __half2 hi = __floats2half2_rn(v.z, v.w);
        uint2 o;
        o.x = *(const uint32_t*)&lo;
        o.y = *(const uint32_t*)&hi;
        dst[idx] = o;
    }
}

// =====================================================================
//  fp16 mma GEMM (R7 config, frozen)
// =====================================================================
#define BMt 128
#define BNt 128
#define BKh 64
#define PADh 72
#define STAGE_H ((BMt + BNt) * PADh)
#define GM_SMEM (3 * STAGE_H * 2)

__device__ __forceinline__ void gemm_f16_body(const __half* __restrict__ A,
                                              const __half* __restrict__ B,
                                              float* __restrict__ C,
                                              int Ncols, int K) {
    extern __shared__ __half smh[];
    const uint32_t sbase = smem_u32(smh);
    const int tid = threadIdx.x, wid = tid >> 5, lane = tid & 31;
    const int g = lane >> 2, q = lane & 3;
    const int m0 = blockIdx.x * BMt;
    const int n0 = blockIdx.y * BNt;
    const int wm = (wid >> 1) * 32;
    const int wn = (wid & 1) * 64;
    const int nk = K / BKh;

    const int a_row = wm + (lane & 15);
    const int a_kh  = ((lane >> 4) & 1) * 8;
    const uint32_t a_off = (uint32_t)(a_row * PADh + a_kh) * 2;
    const int b_nrow = (lane & 7) + ((lane >> 4) & 1) * 8;
    const int b_kh   = ((lane >> 3) & 1) * 8;
    const uint32_t b_off = (uint32_t)(BMt * PADh + (wn + b_nrow) * PADh + b_kh) * 2;

    float acc[2][8][4];
#pragma unroll
    for (int i = 0; i < 2; ++i)
#pragma unroll
        for (int j = 0; j < 8; ++j)
#pragma unroll
            for (int r = 0; r < 4; ++r) acc[i][j][r] = 0.f;

    auto load_stage = [&](int c) {
        const int s = c % 3;
        const int k0 = c * BKh;
        const uint32_t abase = sbase + s * STAGE_H * 2;
        const uint32_t bbase = abase + BMt * PADh * 2;
#pragma unroll
        for (int i = 0; i < 4; ++i) {
            int t = tid + i * 256;
            int r = t >> 3, qq = t & 7;
            cp16(abase + (uint32_t)(r * PADh + qq * 8) * 2,
                 A + (size_t)(m0 + r) * K + k0 + qq * 8);
        }
#pragma unroll
        for (int i = 0; i < 4; ++i) {
            int t = tid + i * 256;
            int r = t >> 3, qq = t & 7;
            cp16(bbase + (uint32_t)(r * PADh + qq * 8) * 2,
                 B + (size_t)(n0 + r) * K + k0 + qq * 8);
        }
        asm volatile("cp.async.commit_group;");
    };

    load_stage(0);
    load_stage(1);

    for (int c = 0; c < nk; ++c) {
        if (c + 1 < nk) {
            asm volatile("cp.async.wait_group 1;");
        } else {
            asm volatile("cp.async.wait_group 0;");
        }
        __syncthreads();

        if (c + 2 < nk) load_stage(c + 2);

        const uint32_t stg = sbase + (uint32_t)(c % 3) * STAGE_H * 2;
        const uint32_t a_addr = stg + a_off;
        const uint32_t b_addr = stg + b_off;

#pragma unroll
        for (int ks = 0; ks < 4; ++ks) {
            const uint32_t kadd = (uint32_t)ks * 32;
            uint32_t af[2][4];
            ldm_x4(af[0], a_addr + kadd);
            ldm_x4(af[1], a_addr + 16 * PADh * 2 + kadd);
            uint32_t bf[4][4];
#pragma unroll
            for (int nb = 0; nb < 4; ++nb)
                ldm_x4(bf[nb], b_addr + (uint32_t)(nb * 16 * PADh) * 2 + kadd);
#pragma unroll
            for (int mi = 0; mi < 2; ++mi)
#pragma unroll
                for (int ni = 0; ni < 8; ++ni)
                    mma_f16(acc[mi][ni], af[mi], &bf[ni >> 1][(ni & 1) * 2]);
        }
    }

#pragma unroll
    for (int mi = 0; mi < 2; ++mi) {
        const int r = m0 + wm + mi * 16 + g;
#pragma unroll
        for (int ni = 0; ni < 8; ++ni) {
            const int cb = n0 + wn + ni * 8 + 2 * q;
            *(float2*)(C + (size_t)r * Ncols + cb) =
                make_float2(acc[mi][ni][0], acc[mi][ni][1]);
            *(float2*)(C + (size_t)(r + 8) * Ncols + cb) =
                make_float2(acc[mi][ni][2], acc[mi][ni][3]);
        }
    }
}

__global__ void __launch_bounds__(256, 2)
gemm1_mma_k() { gemm_f16_body(d_ha, d_hb1, d_proj, PROJC, HIDm); }
__global__ void __launch_bounds__(256, 2)
gemm2_mma_k(float* __restrict__ C) { gemm_f16_body(d_gh, d_hb2, C, HIDm, INTERC); }

// ---------------- fused: sliding-window conv+SiLU || dt warp-scan ----------------
// grid (18, 128): x<10 -> conv (4 ch/thread, 16 l-rows, window slide);
//                 x>=10 -> dt block idx = (x-10)*128 + y (0..1023)
__global__ void __launch_bounds__(256)
conv_dt_k(const float* __restrict__ w, const float* __restrict__ b,
          const float* __restrict__ dt_bias, const float* __restrict__ A_log) {
    if (blockIdx.x < 10) {
        const int c = (blockIdx.x * 256 + threadIdx.x) * 4;
        const int l0 = blockIdx.y * 16;
        float4 w0 = *(const float4*)&w[(c + 0) * 4];
        float4 w1 = *(const float4*)&w[(c + 1) * 4];
        float4 w2 = *(const float4*)&w[(c + 2) * 4];
        float4 w3 = *(const float4*)&w[(c + 3) * 4];
        float4 bv = *(const float4*)&b[c];
        const float* pcol = &d_proj[INTERC + c];
        float4 zero = make_float4(0.f, 0.f, 0.f, 0.f);
        // window: rows l-3, l-2, l-1 (zeros before sequence start)
        float4 r0 = (l0 >= 3) ? *(const float4*)&pcol[(size_t)(l0 - 3) * PROJC] : zero;
        float4 r1 = (l0 >= 2) ? *(const float4*)&pcol[(size_t)(l0 - 2) * PROJC] : zero;
        float4 r2 = (l0 >= 1) ? *(const float4*)&pcol[(size_t)(l0 - 1) * PROJC] : zero;
#pragma unroll 4
        for (int li = 0; li < 16; ++li) {
            const int l = l0 + li;
            float4 cur = *(const float4*)&pcol[(size_t)l * PROJC];
            // acc = b + w[0]*p[l-3] + w[1]*p[l-2] + w[2]*p[l-1] + w[3]*p[l] (same FMA order as before)
            float4 acc = bv;
            acc.x += w0.x * r0.x; acc.y += w1.x * r0.y; acc.z += w2.x * r0.z; acc.w += w3.x * r0.w;
            acc.x += w0.y * r1.x; acc.y += w1.y * r1.y; acc.z += w2.y * r1.z; acc.w += w3.y * r1.w;
            acc.x += w0.z * r2.x; acc.y += w1.z * r2.y; acc.z += w2.z * r2.z; acc.w += w3.z * r2.w;
            acc.x += w0.w * cur.x; acc.y += w1.w * cur.y; acc.z += w2.w * cur.z; acc.w += w3.w * cur.w;
            acc.x = acc.x / (1.f + __expf(-acc.x));
            acc.y = acc.y / (1.f + __expf(-acc.y));
            acc.z = acc.z / (1.f + __expf(-acc.z));
            acc.w = acc.w / (1.f + __expf(-acc.w));
            *(float4*)&d_xbc[(size_t)l * CONVC + c] = acc;
            __half2 lo = __floats2half2_rn(acc.x, acc.y);
            __half2 hi = __floats2half2_rn(acc.z, acc.w);
            uint2 o;
            o.x = *(const uint32_t*)&lo;
            o.y = *(const uint32_t*)&hi;
            *(uint2*)&d_xbch[(size_t)l * CONVC + c] = o;
            r0 = r1; r1 = r2; r2 = cur;
        }
    } else {
        int blk = (blockIdx.x - 10) * 128 + blockIdx.y;
        if (blk >= 1024) return;
        int h = blk & 127, c = blk >> 7, t = threadIdx.x;
        int lane = t & 31, warp = t >> 5;
        int l = c * CSz + t;
        float x = d_proj[(size_t)l * PROJC + (INTERC + CONVC) + h] + dt_bias[h];
        float sp = fmaxf(x, 0.f) + log1pf(expf(-fabsf(x)));
        float dtv = fmaxf(sp, 0.f);
        float A = -expf(A_log[h]);
        float val = dtv * A;
#pragma unroll
        for (int o = 1; o < 32; o <<= 1) {
            float n = __shfl_up_sync(0xffffffffu, val, o);
            if (lane >= o) val += n;
        }
        __shared__ float wsum[8];
        if (lane == 31) wsum[warp] = val;
        __syncthreads();
        if (warp == 0 && lane < 8) {
            float v = wsum[lane];
#pragma unroll
            for (int o = 1; o < 8; o <<= 1) {
                float n = __shfl_up_sync(0xffu, v, o);
                if (lane >= o) v += n;
            }
            wsum[lane] = v;
        }
        __syncthreads();
        float base = (warp > 0) ? wsum[warp - 1] : 0.f;
        d_dt [(size_t)l * Hh + h] = dtv;
        d_cum[(size_t)l * Hh + h] = val + base;
    }
}

// ---------------- fused: intra-chunk (fp16 MMA) || chunk-states (fp16 MMA) ----------------
#define CW 136
#define SW 72
#define IT_HALVES (64 * (2 * CW + 3 * SW))
#define IT_SMEM2  (IT_HALVES * 2 + 3 * 64 * 4)     // 63232 B
__global__ void __launch_bounds__(256, 2)
ssd_intra_states_k() {
    extern __shared__ __align__(16) char sraw[];
    const int h = blockIdx.y, c = blockIdx.z;
    const int g = h >> 4;
    const int tid = threadIdx.x;
    const int wid = tid >> 5, lane = tid & 31;
    const int gq = lane >> 2, q = lane & 3;
    const int mw = wid >> 1;
    const int nw = wid & 1;

    if (blockIdx.x < 4) {
        // ================= intra branch: fp16 tensor-core =================
        __half* Cs  = (__half*)sraw;
        __half* Bs  = Cs + 64 * CW;
        __half* Ss  = Bs + 64 * CW;
        __half* Xs  = Ss + 64 * SW;
        __half* XsT = Xs + 64 * SW;
        float* cum_i = (float*)(XsT + 64 * SW);
        float* cum_j = cum_i + 64;
        float* dtj   = cum_j + 64;

        const int it = blockIdx.x;
        const int li0 = c * CSz + it * 64;
        const int ccol = INTERC + Gg * Nn + g * Nn;
        const int bcol = INTERC + g * Nn;

        const uint32_t CsB = smem_u32(Cs), BsB = smem_u32(Bs);
        const uint32_t SsB = smem_u32(Ss), XtB = smem_u32(XsT);
        const uint32_t aS_off = (uint32_t)((mw * 16 + (lane & 15)) * CW + ((lane >> 4) & 1) * 8) * 2;
        const uint32_t bS_off = (uint32_t)((nw * 32 + (lane & 7) + ((lane >> 4) & 1) * 8) * CW + ((lane >> 3) & 1) * 8) * 2;
        const uint32_t aY_off = (uint32_t)((mw * 16 + (lane & 15)) * SW + ((lane >> 4) & 1) * 8) * 2;
        const uint32_t bY_off = (uint32_t)((nw * 32 + (lane & 7) + ((lane >> 4) & 1) * 8) * SW + ((lane >> 3) & 1) * 8) * 2;

#pragma unroll
        for (int rep = 0; rep < 4; ++rep) {
            int idx = tid + rep * 256;
            int r = idx >> 4, qq = idx & 15;
            *(uint4*)&Cs[r * CW + qq * 8] =
                *(const uint4*)&d_xbch[(size_t)(li0 + r) * CONVC + ccol + qq * 8];
        }
        if (tid < 64) cum_i[tid] = d_cum[(size_t)(li0 + tid) * Hh + h];

        float accY[4][4];
#pragma unroll
        for (int i = 0; i < 4; ++i)
#pragma unroll
            for (int j = 0; j < 4; ++j) accY[i][j] = 0.f;

        const int i0 = mw * 16 + gq;

        for (int jt = 0; jt <= it; ++jt) {
            const int lj0 = c * CSz + jt * 64;
            __syncthreads();
#pragma unroll
            for (int rep = 0; rep < 4; ++rep) {
                int idx = tid + rep * 256;
                int r = idx >> 4, qq = idx & 15;
                *(uint4*)&Bs[r * CW + qq * 8] =
                    *(const uint4*)&d_xbch[(size_t)(lj0 + r) * CONVC + bcol + qq * 8];
            }
#pragma unroll
            for (int rep = 0; rep < 2; ++rep) {
                int idx = tid + rep * 256;
                int r = idx >> 3, qq = idx & 7;
                *(uint4*)&Xs[r * SW + qq * 8] =
                    *(const uint4*)&d_xbch[(size_t)(lj0 + r) * CONVC + h * Pp + qq * 8];
            }
            if (tid < 64) {
                cum_j[tid] = d_cum[(size_t)(lj0 + tid) * Hh + h];
                dtj  [tid] = d_dt [(size_t)(lj0 + tid) * Hh + h];
            }
            __syncthreads();

#pragma unroll
            for (int rep = 0; rep < 4; ++rep) {
                int idx = tid + rep * 256;
                int bb = idx >> 5, aa = idx & 31;
                uint32_t u0 = *(uint32_t*)&Xs[(2 * bb) * SW + 2 * aa];
                uint32_t u1 = *(uint32_t*)&Xs[(2 * bb + 1) * SW + 2 * aa];
                uint32_t lo = (u0 & 0xffffu) | (u1 << 16);
                uint32_t hi = (u0 >> 16) | (u1 & 0xffff0000u);
                *(uint32_t*)&XsT[(2 * aa) * SW + 2 * bb] = lo;
                *(uint32_t*)&XsT[(2 * aa + 1) * SW + 2 * bb] = hi;
            }

            float accS[4][4];
#pragma unroll
            for (int i = 0; i < 4; ++i)
#pragma unroll
                for (int j = 0; j < 4; ++j) accS[i][j] = 0.f;
#pragma unroll
            for (int ks = 0; ks < 8; ++ks) {
                const uint32_t kadd = (uint32_t)ks * 32;
                uint32_t af[4];
                ldm_x4(af, CsB + aS_off + kadd);
                uint32_t bf[2][4];
                ldm_x4(bf[0], BsB + bS_off + kadd);
                ldm_x4(bf[1], BsB + bS_off + (uint32_t)(16 * CW) * 2 + kadd);
#pragma unroll
                for (int ni = 0; ni < 4; ++ni)
                    mma_f16(accS[ni], af, &bf[ni >> 1][(ni & 1) * 2]);
            }

            {
                const float ci0 = cum_i[i0], ci1 = cum_i[i0 + 8];
                const int gi0 = it * 64 + i0, gi1 = gi0 + 8;
#pragma unroll
                for (int ni = 0; ni < 4; ++ni) {
                    int jb = nw * 32 + ni * 8 + 2 * q;
                    float cj0 = cum_j[jb], cj1 = cum_j[jb + 1];
                    float dj0 = dtj[jb],  dj1 = dtj[jb + 1];
                    int gj0 = jt * 64 + jb, gj1 = gj0 + 1;
                    float v00 = (gi0 >= gj0) ? accS[ni][0] * __expf(ci0 - cj0) * dj0 : 0.f;
                    float v01 = (gi0 >= gj1) ? accS[ni][1] * __expf(ci0 - cj1) * dj1 : 0.f;
                    float v10 = (gi1 >= gj0) ? accS[ni][2] * __expf(ci1 - cj0) * dj0 : 0.f;
                    float v11 = (gi1 >= gj1) ? accS[ni][3] * __expf(ci1 - cj1) * dj1 : 0.f;
                    __half2 h0 = __floats2half2_rn(v00, v01);
                    __half2 h1 = __floats2half2_rn(v10, v11);
                    *(__half2*)&Ss[i0 * SW + jb] = h0;
                    *(__half2*)&Ss[(i0 + 8) * SW + jb] = h1;
                }
            }
            __syncthreads();

#pragma unroll
            for (int ks = 0; ks < 4; ++ks) {
                const uint32_t kadd = (uint32_t)ks * 32;
                uint32_t af[4];
                ldm_x4(af, SsB + aY_off + kadd);
                uint32_t bf[2][4];
                ldm_x4(bf[0], XtB + bY_off + kadd);
                ldm_x4(bf[1], XtB + bY_off + (uint32_t)(16 * SW) * 2 + kadd);
#pragma unroll
                for (int ni = 0; ni < 4; ++ni)
                    mma_f16(accY[ni], af, &bf[ni >> 1][(ni & 1) * 2]);
            }
        }

#pragma unroll
        for (int ni = 0; ni < 4; ++ni) {
            int p = nw * 32 + ni * 8 + 2 * q;
            *(float2*)&d_y[(size_t)(li0 + i0) * INTERC + h * Pp + p] =
                make_float2(accY[ni][0], accY[ni][1]);
            *(float2*)&d_y[(size_t)(li0 + i0 + 8) * INTERC + h * Pp + p] =
                make_float2(accY[ni][2], accY[ni][3]);
        }
    } else {
        // ============== states branch: fp16 tensor-core ==============
        float*  Xsf = (float*)sraw;                 // [64 j][68 p] fp32
        __half* WXT = (__half*)(Xsf + 64 * 68);     // [64 p][72 j]
        __half* Bs2 = WXT + 64 * SW;                // [64 j][136 n]
        __half* BT  = Bs2 + 64 * CW;                // [128 n][72 j]
        float*  ws  = (float*)(BT + 128 * SW);      // [64]

        const uint32_t WxB = smem_u32(WXT), BtB = smem_u32(BT);
        const uint32_t aT_off = (uint32_t)((mw * 16 + (lane & 15)) * SW + ((lane >> 4) & 1) * 8) * 2;
        const uint32_t bT_off = (uint32_t)((nw * 64 + (lane & 7) + ((lane >> 4) & 1) * 8) * SW + ((lane >> 3) & 1) * 8) * 2;

        const float cum_last = d_cum[(size_t)(c * CSz + CSz - 1) * Hh + h];

        float acc[8][4];
#pragma unroll
        for (int i = 0; i < 8; ++i)
#pragma unroll
            for (int j = 0; j < 4; ++j) acc[i][j] = 0.f;

        for (int j0 = 0; j0 < CSz; j0 += 64) {
            __syncthreads();
#pragma unroll
            for (int rep = 0; rep < 4; ++rep) {
                int idx = tid + rep * 256;
                int r = idx >> 4, qn = idx & 15;
                *(float4*)&Xsf[r * 68 + qn * 4] =
                    *(const float4*)&d_xbc[(size_t)(c * CSz + j0 + r) * CONVC + h * Pp + qn * 4];
            }
#pragma unroll
            for (int rep = 0; rep < 4; ++rep) {
                int idx = tid + rep * 256;
                int r = idx >> 4, qq = idx & 15;
                *(uint4*)&Bs2[r * CW + qq * 8] =
                    *(const uint4*)&d_xbch[(size_t)(c * CSz + j0 + r) * CONVC + INTERC + g * Nn + qq * 8];
            }
            if (tid < 64) {
                int l = c * CSz + j0 + tid;
                ws[tid] = d_dt[(size_t)l * Hh + h] * __expf(cum_last - d_cum[(size_t)l * Hh + h]);
            }
            __syncthreads();

#pragma unroll
            for (int rep = 0; rep < 4; ++rep) {
                int idx = tid + rep * 256;
                int jb = idx >> 5, pb = idx & 31;
                float2 a0 = *(const float2*)&Xsf[(2 * jb) * 68 + 2 * pb];
                float2 a1 = *(const float2*)&Xsf[(2 * jb + 1) * 68 + 2 * pb];
                float w0 = ws[2 * jb], w1 = ws[2 * jb + 1];
                *(__half2*)&WXT[(2 * pb) * SW + 2 * jb]     = __floats2half2_rn(w0 * a0.x, w1 * a1.x);
                *(__half2*)&WXT[(2 * pb + 1) * SW + 2 * jb] = __floats2half2_rn(w0 * a0.y, w1 * a1.y);
            }
#pragma unroll
            for (int rep = 0; rep < 8; ++rep) {
                int idx = tid + rep * 256;
                int jb = idx >> 6, nb2 = idx & 63;
                uint32_t u0 = *(uint32_t*)&Bs2[(2 * jb) * CW + 2 * nb2];
                uint32_t u1 = *(uint32_t*)&Bs2[(2 * jb + 1) * CW + 2 * nb2];
                uint32_t lo = (u0 & 0xffffu) | (u1 << 16);
                uint32_t hi = (u0 >> 16) | (u1 & 0xffff0000u);
                *(uint32_t*)&BT[(2 * nb2) * SW + 2 * jb] = lo;
                *(uint32_t*)&BT[(2 * nb2 + 1) * SW + 2 * jb] = hi;
            }
            __syncthreads();

#pragma unroll
            for (int ks = 0; ks < 4; ++ks) {
                const uint32_t kadd = (uint32_t)ks * 32;
                uint32_t af[4];
                ldm_x4(af, WxB + aT_off + kadd);
                uint32_t bf[4][4];
#pragma unroll
                for (int nb = 0; nb < 4; ++nb)
                    ldm_x4(bf[nb], BtB + bT_off + (uint32_t)(nb * 16 * SW) * 2 + kadd);
#pragma unroll
                for (int ni = 0; ni < 8; ++ni)
                    mma_f16(acc[ni], af, &bf[ni >> 1][(ni & 1) * 2]);
            }
        }

        const int p0 = mw * 16 + gq;
#pragma unroll
        for (int ni = 0; ni < 8; ++ni) {
            int nn = nw * 64 + ni * 8 + 2 * q;
            size_t b0 = ((size_t)(c * Hh + h) * Pp + p0) * Nn + nn;
            size_t b1 = ((size_t)(c * Hh + h) * Pp + p0 + 8) * Nn + nn;
            *(float2*)&d_st[b0] = make_float2(acc[ni][0], acc[ni][1]);
            *(float2*)&d_st[b1] = make_float2(acc[ni][2], acc[ni][3]);
        }
    }
}

// ---------------- inter-chunk scan (float2, writes fp16 prev) ----------------
__global__ void __launch_bounds__(256)
ssd_scan_k() {
    int idx2 = blockIdx.x * 256 + threadIdx.x;
    if (idx2 >= Hh * Pp * Nn / 2) return;
    int idx = idx2 * 2;
    int h = idx / (Pp * Nn);
    float2 carry = make_float2(0.f, 0.f);
#pragma unroll
    for (int c = 0; c < NC; ++c) {
        __half2 ph = __floats2half2_rn(carry.x, carry.y);
        *(__half2*)&d_prevh[(size_t)c * Hh * Pp * Nn + idx] = ph;
        float cdec = __expf(d_cum[(size_t)(c * CSz + CSz - 1) * Hh + h]);
        float2 st = *(const float2*)&d_st[(size_t)c * Hh * Pp * Nn + idx];
        carry.x = cdec * carry.x + st.x;
        carry.y = cdec * carry.y + st.y;
    }
}

// ---------------- inter-chunk output (fp16 MMA) + D*x ----------------
__global__ void __launch_bounds__(256)
ssd_inter_k(const float* __restrict__ Dp) {
    __shared__ __align__(16) __half Cs[64 * CW];
    __shared__ __align__(16) __half Ph[64 * CW];
    __shared__ float cum_i[64];

    const int it = blockIdx.x, h = blockIdx.y, c = blockIdx.z;
    const int g = h >> 4;
    const int tid = threadIdx.x;
    const int wid = tid >> 5, lane = tid & 31;
    const int gq = lane >> 2, q = lane & 3;
    const int mw = wid >> 1;
    const int nw = wid & 1;

    const int li0 = c * CSz + it * 64;
    const int ccol = INTERC + Gg * Nn + g * Nn;
    const size_t pbase = ((size_t)(c * Hh + h) * Pp) * Nn;

#pragma unroll
    for (int rep = 0; rep < 4; ++rep) {
        int idx = tid + rep * 256;
        int r = idx >> 4, qq = idx & 15;
        *(uint4*)&Cs[r * CW + qq * 8] =
            *(const uint4*)&d_xbch[(size_t)(li0 + r) * CONVC + ccol + qq * 8];
        *(uint4*)&Ph[r * CW + qq * 8] =
            *(const uint4*)&d_prevh[pbase + (size_t)r * Nn + qq * 8];
    }
    if (tid < 64) cum_i[tid] = d_cum[(size_t)(li0 + tid) * Hh + h];
    __syncthreads();

    const uint32_t CsB = smem_u32(Cs), PhB = smem_u32(Ph);
    const uint32_t a_off = (uint32_t)((mw * 16 + (lane & 15)) * CW + ((lane >> 4) & 1) * 8) * 2;
    const uint32_t b_off = (uint32_t)((nw * 32 + (lane & 7) + ((lane >> 4) & 1) * 8) * CW + ((lane >> 3) & 1) * 8) * 2;

    float acc[4][4];
#pragma unroll
    for (int i = 0; i < 4; ++i)
#pragma unroll
        for (int j = 0; j < 4; ++j) acc[i][j] = 0.f;

#pragma unroll
    for (int ks = 0; ks < 8; ++ks) {
        const uint32_t kadd = (uint32_t)ks * 32;
        uint32_t af[4];
        ldm_x4(af, CsB + a_off + kadd);
        uint32_t bf[2][4];
        ldm_x4(bf[0], PhB + b_off + kadd);
        ldm_x4(bf[1], PhB + b_off + (uint32_t)(16 * CW) * 2 + kadd);
#pragma unroll
        for (int ni = 0; ni < 4; ++ni)
            mma_f16(acc[ni], af, &bf[ni >> 1][(ni & 1) * 2]);
    }

    const int i0 = mw * 16 + gq;
    const float esc0 = __expf(cum_i[i0]);
    const float esc1 = __expf(cum_i[i0 + 8]);
    const float Dh = Dp[h];
#pragma unroll
    for (int ni = 0; ni < 4; ++ni) {
        int p = nw * 32 + ni * 8 + 2 * q;
        size_t y0 = (size_t)(li0 + i0) * INTERC + h * Pp + p;
        size_t y1 = (size_t)(li0 + i0 + 8) * INTERC + h * Pp + p;
        size_t x0 = (size_t)(li0 + i0) * CONVC + h * Pp + p;
        size_t x1 = (size_t)(li0 + i0 + 8) * CONVC + h * Pp + p;
        float2 yv0 = *(const float2*)&d_y[y0];
        float2 yv1 = *(const float2*)&d_y[y1];
        float2 xv0 = *(const float2*)&d_xbc[x0];
        float2 xv1 = *(const float2*)&d_xbc[x1];
        yv0.x += esc0 * acc[ni][0] + Dh * xv0.x;
        yv0.y += esc0 * acc[ni][1] + Dh * xv0.y;
        yv1.x += esc1 * acc[ni][2] + Dh * xv1.x;
        yv1.y += esc1 * acc[ni][3] + Dh * xv1.y;
        *(float2*)&d_y[y0] = yv0;
        *(float2*)&d_y[y1] = yv1;
    }
}

// ---------------- gated RMS group-norm (writes fp16 d_gh) ----------------
__global__ void __launch_bounds__(256)
gated_norm_k(const float* __restrict__ norm_w) {
    const int l = blockIdx.x, grp = blockIdx.y;
    const int tid = threadIdx.x;
    float v[4];
    float ss = 0.f;
#pragma unroll
    for (int i = 0; i < 4; ++i) {
        int col = grp * GSZ + tid + i * 256;
        float gate = d_proj[(size_t)l * PROJC + col];
        float yv = d_y[(size_t)l * INTERC + col];
        float sg = gate / (1.f + __expf(-gate));
        v[i] = yv * sg;
        ss += v[i] * v[i];
    }
#pragma unroll
    for (int off = 16; off; off >>= 1) ss += __shfl_xor_sync(0xffffffffu, ss, off);
    __shared__ float red[8];
    if ((tid & 31) == 0) red[tid >> 5] = ss;
    __syncthreads();
    float tot = red[0] + red[1] + red[2] + red[3] + red[4] + red[5] + red[6] + red[7];
    float rs = rsqrtf(tot / (float)GSZ + EPSf);
#pragma unroll
    for (int i = 0; i < 4; ++i) {
        int col = grp * GSZ + tid + i * 256;
        d_gh[(size_t)l * INTERC + col] = __float2half_rn(v[i] * rs * norm_w[col]);
    }
}

// ---------------- launch ----------------
extern "C" void kernel_launch(void* const* d_in, const int* in_sizes, int n_in,
                              void* d_out, int out_size) {
    const float* input     = (const float*)d_in[0];
    const float* in_proj_w = (const float*)d_in[1];
    const float* conv_w    = (const float*)d_in[2];
    const float* conv_b    = (const float*)d_in[3];
    const float* dt_bias   = (const float*)d_in[4];
    const float* A_log     = (const float*)d_in[5];
    const float* Dp        = (const float*)d_in[6];
    const float* norm_w    = (const float*)d_in[7];
    const float* out_w     = (const float*)d_in[8];
    float* out = (float*)d_out;

    cudaFuncSetAttribute(gemm1_mma_k, cudaFuncAttributeMaxDynamicSharedMemorySize, GM_SMEM);
    cudaFuncSetAttribute(gemm2_mma_k, cudaFuncAttributeMaxDynamicSharedMemorySize, GM_SMEM);
    cudaFuncSetAttribute(ssd_intra_states_k, cudaFuncAttributeMaxDynamicSharedMemorySize, IT_SMEM2);

    __half* ha;  cudaGetSymbolAddress((void**)&ha,  d_ha);
    __half* hb1; cudaGetSymbolAddress((void**)&hb1, d_hb1);
    __half* hb2; cudaGetSymbolAddress((void**)&hb2, d_hb2);

    // 0. merged fp16 pre-convert (grid-stride)
    cvt_all_k<<<4096, 256>>>((const float4*)input, (uint2*)ha,
                             (const float4*)in_proj_w, (uint2*)hb1,
                             (const float4*)out_w, (uint2*)hb2);

    // 1. in_proj GEMM (fp16 mma)
    gemm1_mma_k<<<dim3(Lq / BMt, PROJC / BNt), 256, GM_SMEM>>>();
    // 2. fused sliding-window conv+SiLU || dt warp-scan
    conv_dt_k<<<dim3(18, 128), 256>>>(conv_w, conv_b, dt_bias, A_log);
    // 3. fused intra-chunk (fp16 MMA) || chunk-states (fp16 MMA)
    ssd_intra_states_k<<<dim3(5, Hh, NC), 256, IT_SMEM2>>>();
    // 4. inter-chunk sequential scan -> d_prevh (fp16)
    ssd_scan_k<<<(Hh * Pp * Nn / 2 + 255) / 256, 256>>>();
    // 5. inter-chunk contribution (fp16 MMA) + D*x -> d_y (final)
    ssd_inter_k<<<dim3(4, Hh, NC), 256>>>(Dp);
    // 6. gated RMS group-norm -> d_gh (fp16)
    gated_norm_k<<<dim3(Lq, Gg), 256>>>(norm_w);
    // 7. out GEMM (fp16 mma)
    gemm2_mma_k<<<dim3(Lq / BMt, HIDm / BNt), 256, GM_SMEM>>>(out);
}

// round 16
// speedup vs baseline: 1.1228x; 1.0236x over previous
#include <cuda_runtime.h>
#include <cuda_fp16.h>
#include <math.h>
#include <stdint.h>

// ---------------- problem constants ----------------
#define Lq     2048
#define HIDm   4096
#define Hh     128
#define Pp     64
#define Nn     128
#define Gg     8
#define Kk     4
#define CSz    256
#define NC     8            // L / CS
#define INTERC 8192         // H*P
#define CONVC  10240        // INTER + 2*G*N
#define PROJC  18560        // INTER + CONV + H
#define GSZ    1024         // INTER / G
#define EPSf   1e-5f

// ---------------- scratch (static device globals; no allocation) ----------------
__device__ float d_proj[(size_t)Lq * PROJC];
__device__ float d_xbc [(size_t)Lq * CONVC];
__device__ float d_dt  [(size_t)Lq * Hh];
__device__ float d_cum [(size_t)Lq * Hh];
__device__ float d_y   [(size_t)Lq * INTERC];
__device__ float d_st  [(size_t)NC * Hh * Pp * Nn];
// fp16 operands
__device__ __align__(16) __half d_ha   [(size_t)Lq * HIDm];
__device__ __align__(16) __half d_hb1  [(size_t)PROJC * HIDm];
__device__ __align__(16) __half d_hb2  [(size_t)HIDm * INTERC];
__device__ __align__(16) __half d_gh   [(size_t)Lq * INTERC];
__device__ __align__(16) __half d_xbch [(size_t)Lq * CONVC];
__device__ __align__(16) __half d_prevh[(size_t)NC * Hh * Pp * Nn];

__device__ __forceinline__ uint32_t smem_u32(const void* p) {
    return (uint32_t)__cvta_generic_to_shared(p);
}
__device__ __forceinline__ void cp16(uint32_t dst, const void* src) {
    asm volatile("cp.async.cg.shared.global [%0], [%1], 16;\n" :: "r"(dst), "l"(src));
}
__device__ __forceinline__ void mma_f16(float* c, const uint32_t* a, const uint32_t* b) {
    asm volatile(
        "mma.sync.aligned.m16n8k16.row.col.f32.f16.f16.f32 "
        "{%0,%1,%2,%3}, {%4,%5,%6,%7}, {%8,%9}, {%0,%1,%2,%3};"
        : "+f"(c[0]), "+f"(c[1]), "+f"(c[2]), "+f"(c[3])
        : "r"(a[0]), "r"(a[1]), "r"(a[2]), "r"(a[3]), "r"(b[0]), "r"(b[1]));
}
__device__ __forceinline__ void ldm_x4(uint32_t* r, uint32_t addr) {
    asm volatile("ldmatrix.sync.aligned.m8n8.x4.shared.b16 {%0,%1,%2,%3}, [%4];"
                 : "=r"(r[0]), "=r"(r[1]), "=r"(r[2]), "=r"(r[3]) : "r"(addr));
}
__device__ __forceinline__ void ldm_x4_t(uint32_t* r, uint32_t addr) {
    asm volatile("ldmatrix.sync.aligned.m8n8.x4.trans.shared.b16 {%0,%1,%2,%3}, [%4];"
                 : "=r"(r[0]), "=r"(r[1]), "=r"(r[2]), "=r"(r[3]) : "r"(addr));
}

// ---------------- merged fp32 -> fp16 pre-convert (ha + hb1 only) ----------------
#define N4_A  (Lq * HIDm / 4)
#define N4_B1 (PROJC * HIDm / 4)
#define N4_B2 (HIDm * INTERC / 4)
__global__ void __launch_bounds__(256)
cvt_all_k(const float4* __restrict__ inA, uint2* __restrict__ outA,
          const float4* __restrict__ inB1, uint2* __restrict__ outB1) {
    const int total = N4_A + N4_B1;
    for (int i = blockIdx.x * 256 + threadIdx.x; i < total; i += gridDim.x * 256) {
        const float4* src;
        uint2* dst;
        int idx;
        if (i < N4_A) { src = inA;  dst = outA;  idx = i; }
        else          { src = inB1; dst = outB1; idx = i - N4_A; }
        float4 v = src[idx];
        __half2 lo = __floats2half2_rn(v.x, v.y);
        __half2 hi = __floats2half2_rn(v.z, v.w);
        uint2 o;
        o.x = *(const uint32_t*)&lo;
        o.y = *(const uint32_t*)&hi;
        dst[idx] = o;
    }
}

// =====================================================================
//  fp16 mma GEMM (R7 config, frozen)
// =====================================================================
#define BMt 128
#define BNt 128
#define BKh 64
#define PADh 72
#define STAGE_H ((BMt + BNt) * PADh)
#define GM_SMEM (3 * STAGE_H * 2)

__device__ __forceinline__ void gemm_f16_body(const __half* __restrict__ A,
                                              const __half* __restrict__ B,
                                              float* __restrict__ C,
                                              int Ncols, int K) {
    extern __shared__ __half smh[];
    const uint32_t sbase = smem_u32(smh);
    const int tid = threadIdx.x, wid = tid >> 5, lane = tid & 31;
    const int g = lane >> 2, q = lane & 3;
    const int m0 = blockIdx.x * BMt;
    const int n0 = blockIdx.y * BNt;
    const int wm = (wid >> 1) * 32;
    const int wn = (wid & 1) * 64;
    const int nk = K / BKh;

    const int a_row = wm + (lane & 15);
    const int a_kh  = ((lane >> 4) & 1) * 8;
    const uint32_t a_off = (uint32_t)(a_row * PADh + a_kh) * 2;
    const int b_nrow = (lane & 7) + ((lane >> 4) & 1) * 8;
    const int b_kh   = ((lane >> 3) & 1) * 8;
    const uint32_t b_off = (uint32_t)(BMt * PADh + (wn + b_nrow) * PADh + b_kh) * 2;

    float acc[2][8][4];
#pragma unroll
    for (int i = 0; i < 2; ++i)
#pragma unroll
        for (int j = 0; j < 8; ++j)
#pragma unroll
            for (int r = 0; r < 4; ++r) acc[i][j][r] = 0.f;

    auto load_stage = [&](int c) {
        const int s = c % 3;
        const int k0 = c * BKh;
        const uint32_t abase = sbase + s * STAGE_H * 2;
        const uint32_t bbase = abase + BMt * PADh * 2;
#pragma unroll
        for (int i = 0; i < 4; ++i) {
            int t = tid + i * 256;
            int r = t >> 3, qq = t & 7;
            cp16(abase + (uint32_t)(r * PADh + qq * 8) * 2,
                 A + (size_t)(m0 + r) * K + k0 + qq * 8);
        }
#pragma unroll
        for (int i = 0; i < 4; ++i) {
            int t = tid + i * 256;
            int r = t >> 3, qq = t & 7;
            cp16(bbase + (uint32_t)(r * PADh + qq * 8) * 2,
                 B + (size_t)(n0 + r) * K + k0 + qq * 8);
        }
        asm volatile("cp.async.commit_group;");
    };

    load_stage(0);
    load_stage(1);

    for (int c = 0; c < nk; ++c) {
        if (c + 1 < nk) {
            asm volatile("cp.async.wait_group 1;");
        } else {
            asm volatile("cp.async.wait_group 0;");
        }
        __syncthreads();

        if (c + 2 < nk) load_stage(c + 2);

        const uint32_t stg = sbase + (uint32_t)(c % 3) * STAGE_H * 2;
        const uint32_t a_addr = stg + a_off;
        const uint32_t b_addr = stg + b_off;

#pragma unroll
        for (int ks = 0; ks < 4; ++ks) {
            const uint32_t kadd = (uint32_t)ks * 32;
            uint32_t af[2][4];
            ldm_x4(af[0], a_addr + kadd);
            ldm_x4(af[1], a_addr + 16 * PADh * 2 + kadd);
            uint32_t bf[4][4];
#pragma unroll
            for (int nb = 0; nb < 4; ++nb)
                ldm_x4(bf[nb], b_addr + (uint32_t)(nb * 16 * PADh) * 2 + kadd);
#pragma unroll
            for (int mi = 0; mi < 2; ++mi)
#pragma unroll
                for (int ni = 0; ni < 8; ++ni)
                    mma_f16(acc[mi][ni], af[mi], &bf[ni >> 1][(ni & 1) * 2]);
        }
    }

#pragma unroll
    for (int mi = 0; mi < 2; ++mi) {
        const int r = m0 + wm + mi * 16 + g;
#pragma unroll
        for (int ni = 0; ni < 8; ++ni) {
            const int cb = n0 + wn + ni * 8 + 2 * q;
            *(float2*)(C + (size_t)r * Ncols + cb) =
                make_float2(acc[mi][ni][0], acc[mi][ni][1]);
            *(float2*)(C + (size_t)(r + 8) * Ncols + cb) =
                make_float2(acc[mi][ni][2], acc[mi][ni][3]);
        }
    }
}

__global__ void __launch_bounds__(256, 2)
gemm1_mma_k() { gemm_f16_body(d_ha, d_hb1, d_proj, PROJC, HIDm); }
__global__ void __launch_bounds__(256, 2)
gemm2_mma_k(float* __restrict__ C) { gemm_f16_body(d_gh, d_hb2, C, HIDm, INTERC); }

// ---------------- fused: conv+SiLU || dt warp-scan || hb2 cvt ----------------
// grid (26, 128): x<10 conv; 10<=x<18 dt; x>=18 hb2 convert (1024 blocks)
__global__ void __launch_bounds__(256)
conv_dt_k(const float* __restrict__ w, const float* __restrict__ b,
          const float* __restrict__ dt_bias, const float* __restrict__ A_log,
          const float4* __restrict__ w2in, uint2* __restrict__ w2out) {
    if (blockIdx.x < 10) {
        const int c = (blockIdx.x * 256 + threadIdx.x) * 4;
        const int l0 = blockIdx.y * 16;
        float4 w0 = *(const float4*)&w[(c + 0) * 4];
        float4 w1 = *(const float4*)&w[(c + 1) * 4];
        float4 w2 = *(const float4*)&w[(c + 2) * 4];
        float4 w3 = *(const float4*)&w[(c + 3) * 4];
        float4 bv = *(const float4*)&b[c];
        const float* pcol = &d_proj[INTERC + c];
        float4 zero = make_float4(0.f, 0.f, 0.f, 0.f);
        float4 r0 = (l0 >= 3) ? *(const float4*)&pcol[(size_t)(l0 - 3) * PROJC] : zero;
        float4 r1 = (l0 >= 2) ? *(const float4*)&pcol[(size_t)(l0 - 2) * PROJC] : zero;
        float4 r2 = (l0 >= 1) ? *(const float4*)&pcol[(size_t)(l0 - 1) * PROJC] : zero;
#pragma unroll 4
        for (int li = 0; li < 16; ++li) {
            const int l = l0 + li;
            float4 cur = *(const float4*)&pcol[(size_t)l * PROJC];
            float4 acc = bv;
            acc.x += w0.x * r0.x; acc.y += w1.x * r0.y; acc.z += w2.x * r0.z; acc.w += w3.x * r0.w;
            acc.x += w0.y * r1.x; acc.y += w1.y * r1.y; acc.z += w2.y * r1.z; acc.w += w3.y * r1.w;
            acc.x += w0.z * r2.x; acc.y += w1.z * r2.y; acc.z += w2.z * r2.z; acc.w += w3.z * r2.w;
            acc.x += w0.w * cur.x; acc.y += w1.w * cur.y; acc.z += w2.w * cur.z; acc.w += w3.w * cur.w;
            acc.x = acc.x / (1.f + __expf(-acc.x));
            acc.y = acc.y / (1.f + __expf(-acc.y));
            acc.z = acc.z / (1.f + __expf(-acc.z));
            acc.w = acc.w / (1.f + __expf(-acc.w));
            *(float4*)&d_xbc[(size_t)l * CONVC + c] = acc;
            __half2 lo = __floats2half2_rn(acc.x, acc.y);
            __half2 hi = __floats2half2_rn(acc.z, acc.w);
            uint2 o;
            o.x = *(const uint32_t*)&lo;
            o.y = *(const uint32_t*)&hi;
            *(uint2*)&d_xbch[(size_t)l * CONVC + c] = o;
            r0 = r1; r1 = r2; r2 = cur;
        }
    } else if (blockIdx.x < 18) {
        int blk = (blockIdx.x - 10) * 128 + blockIdx.y;
        int h = blk & 127, c = blk >> 7, t = threadIdx.x;
        int lane = t & 31, warp = t >> 5;
        int l = c * CSz + t;
        float x = d_proj[(size_t)l * PROJC + (INTERC + CONVC) + h] + dt_bias[h];
        float sp = fmaxf(x, 0.f) + log1pf(expf(-fabsf(x)));
        float dtv = fmaxf(sp, 0.f);
        float A = -expf(A_log[h]);
        float val = dtv * A;
#pragma unroll
        for (int o = 1; o < 32; o <<= 1) {
            float n = __shfl_up_sync(0xffffffffu, val, o);
            if (lane >= o) val += n;
        }
        __shared__ float wsum[8];
        if (lane == 31) wsum[warp] = val;
        __syncthreads();
        if (warp == 0 && lane < 8) {
            float v = wsum[lane];
#pragma unroll
            for (int o = 1; o < 8; o <<= 1) {
                float n = __shfl_up_sync(0xffu, v, o);
                if (lane >= o) v += n;
            }
            wsum[lane] = v;
        }
        __syncthreads();
        float base = (warp > 0) ? wsum[warp - 1] : 0.f;
        d_dt [(size_t)l * Hh + h] = dtv;
        d_cum[(size_t)l * Hh + h] = val + base;
    } else {
        // hb2 convert: 1024 blocks x 256 threads, strided over N4_B2
        int blk = (blockIdx.x - 18) * 128 + blockIdx.y;
        for (int i = blk * 256 + threadIdx.x; i < N4_B2; i += 1024 * 256) {
            float4 v = w2in[i];
            __half2 lo = __floats2half2_rn(v.x, v.y);
            __half2 hi = __floats2half2_rn(v.z, v.w);
            uint2 o;
            o.x = *(const uint32_t*)&lo;
            o.y = *(const uint32_t*)&hi;
            w2out[i] = o;
        }
    }
}

// ---------------- fused: intra-chunk (fp16 MMA) || chunk-states (fp16 MMA) ----------------
#define CW 136
#define SW 72
#define IT_HALVES (64 * (2 * CW + 3 * SW))
#define IT_SMEM2  (IT_HALVES * 2 + 3 * 64 * 4)     // keep prior (max) size
__global__ void __launch_bounds__(256, 2)
ssd_intra_states_k() {
    extern __shared__ __align__(16) char sraw[];
    const int h = blockIdx.y, c = blockIdx.z;
    const int g = h >> 4;
    const int tid = threadIdx.x;
    const int wid = tid >> 5, lane = tid & 31;
    const int gq = lane >> 2, q = lane & 3;
    const int mw = wid >> 1;
    const int nw = wid & 1;

    if (blockIdx.x < 4) {
        // ================= intra branch: fp16 tensor-core =================
        __half* Cs  = (__half*)sraw;       // [i][n] 64x136
        __half* Bs  = Cs + 64 * CW;        // [j][n] 64x136
        __half* Ss  = Bs + 64 * CW;        // [i][j] 64x72
        __half* Xs  = Ss + 64 * SW;        // [j][p] 64x72  (read via trans-ldmatrix)
        float* cum_i = (float*)(Xs + 64 * SW);
        float* cum_j = cum_i + 64;
        float* dtj   = cum_j + 64;

        const int it = blockIdx.x;
        const int li0 = c * CSz + it * 64;
        const int ccol = INTERC + Gg * Nn + g * Nn;
        const int bcol = INTERC + g * Nn;

        const uint32_t CsB = smem_u32(Cs), BsB = smem_u32(Bs);
        const uint32_t SsB = smem_u32(Ss), XsB = smem_u32(Xs);
        const uint32_t aS_off = (uint32_t)((mw * 16 + (lane & 15)) * CW + ((lane >> 4) & 1) * 8) * 2;
        const uint32_t bS_off = (uint32_t)((nw * 32 + (lane & 7) + ((lane >> 4) & 1) * 8) * CW + ((lane >> 3) & 1) * 8) * 2;
        const uint32_t aY_off = (uint32_t)((mw * 16 + (lane & 15)) * SW + ((lane >> 4) & 1) * 8) * 2;
        // trans B-operand from Xs[j][p]: rows=j, cols=p
        const uint32_t bYt_off = (uint32_t)(((lane & 7) + ((lane >> 3) & 1) * 8) * SW
                                            + nw * 32 + ((lane >> 4) & 1) * 8) * 2;

#pragma unroll
        for (int rep = 0; rep < 4; ++rep) {
            int idx = tid + rep * 256;
            int r = idx >> 4, qq = idx & 15;
            *(uint4*)&Cs[r * CW + qq * 8] =
                *(const uint4*)&d_xbch[(size_t)(li0 + r) * CONVC + ccol + qq * 8];
        }
        if (tid < 64) cum_i[tid] = d_cum[(size_t)(li0 + tid) * Hh + h];

        float accY[4][4];
#pragma unroll
        for (int i = 0; i < 4; ++i)
#pragma unroll
            for (int j = 0; j < 4; ++j) accY[i][j] = 0.f;

        const int i0 = mw * 16 + gq;

        for (int jt = 0; jt <= it; ++jt) {
            const int lj0 = c * CSz + jt * 64;
            __syncthreads();
#pragma unroll
            for (int rep = 0; rep < 4; ++rep) {
                int idx = tid + rep * 256;
                int r = idx >> 4, qq = idx & 15;
                *(uint4*)&Bs[r * CW + qq * 8] =
                    *(const uint4*)&d_xbch[(size_t)(lj0 + r) * CONVC + bcol + qq * 8];
            }
#pragma unroll
            for (int rep = 0; rep < 2; ++rep) {
                int idx = tid + rep * 256;
                int r = idx >> 3, qq = idx & 7;
                *(uint4*)&Xs[r * SW + qq * 8] =
                    *(const uint4*)&d_xbch[(size_t)(lj0 + r) * CONVC + h * Pp + qq * 8];
            }
            if (tid < 64) {
                cum_j[tid] = d_cum[(size_t)(lj0 + tid) * Hh + h];
                dtj  [tid] = d_dt [(size_t)(lj0 + tid) * Hh + h];
            }
            __syncthreads();

            float accS[4][4];
#pragma unroll
            for (int i = 0; i < 4; ++i)
#pragma unroll
                for (int j = 0; j < 4; ++j) accS[i][j] = 0.f;
#pragma unroll
            for (int ks = 0; ks < 8; ++ks) {
                const uint32_t kadd = (uint32_t)ks * 32;
                uint32_t af[4];
                ldm_x4(af, CsB + aS_off + kadd);
                uint32_t bf[2][4];
                ldm_x4(bf[0], BsB + bS_off + kadd);
                ldm_x4(bf[1], BsB + bS_off + (uint32_t)(16 * CW) * 2 + kadd);
#pragma unroll
                for (int ni = 0; ni < 4; ++ni)
                    mma_f16(accS[ni], af, &bf[ni >> 1][(ni & 1) * 2]);
            }

            {
                const float ci0 = cum_i[i0], ci1 = cum_i[i0 + 8];
                const int gi0 = it * 64 + i0, gi1 = gi0 + 8;
#pragma unroll
                for (int ni = 0; ni < 4; ++ni) {
                    int jb = nw * 32 + ni * 8 + 2 * q;
                    float cj0 = cum_j[jb], cj1 = cum_j[jb + 1];
                    float dj0 = dtj[jb],  dj1 = dtj[jb + 1];
                    int gj0 = jt * 64 + jb, gj1 = gj0 + 1;
                    float v00 = (gi0 >= gj0) ? accS[ni][0] * __expf(ci0 - cj0) * dj0 : 0.f;
                    float v01 = (gi0 >= gj1) ? accS[ni][1] * __expf(ci0 - cj1) * dj1 : 0.f;
                    float v10 = (gi1 >= gj0) ? accS[ni][2] * __expf(ci1 - cj0) * dj0 : 0.f;
                    float v11 = (gi1 >= gj1) ? accS[ni][3] * __expf(ci1 - cj1) * dj1 : 0.f;
                    __half2 h0 = __floats2half2_rn(v00, v01);
                    __half2 h1 = __floats2half2_rn(v10, v11);
                    *(__half2*)&Ss[i0 * SW + jb] = h0;
                    *(__half2*)&Ss[(i0 + 8) * SW + jb] = h1;
                }
            }
            __syncthreads();

            // Y += S' @ X : B-operand via trans-ldmatrix straight from Xs[j][p]
#pragma unroll
            for (int ks = 0; ks < 4; ++ks) {
                const uint32_t kadd = (uint32_t)ks * 32;               // A: 16 j-halves
                uint32_t af[4];
                ldm_x4(af, SsB + aY_off + kadd);
                uint32_t bf[2][4];
                const uint32_t jrow = (uint32_t)(ks * 16 * SW) * 2;    // B: 16 j-rows
                ldm_x4_t(bf[0], XsB + bYt_off + jrow);
                ldm_x4_t(bf[1], XsB + bYt_off + jrow + 32);            // +16 p cols
#pragma unroll
                for (int ni = 0; ni < 4; ++ni)
                    mma_f16(accY[ni], af, &bf[ni >> 1][(ni & 1) * 2]);
            }
        }

#pragma unroll
        for (int ni = 0; ni < 4; ++ni) {
            int p = nw * 32 + ni * 8 + 2 * q;
            *(float2*)&d_y[(size_t)(li0 + i0) * INTERC + h * Pp + p] =
                make_float2(accY[ni][0], accY[ni][1]);
            *(float2*)&d_y[(size_t)(li0 + i0 + 8) * INTERC + h * Pp + p] =
                make_float2(accY[ni][2], accY[ni][3]);
        }
    } else {
        // ============== states branch: fp16 tensor-core ==============
        float*  Xsf = (float*)sraw;                 // [64 j][68 p] fp32
        __half* WXT = (__half*)(Xsf + 64 * 68);     // [64 p][72 j]
        __half* Bs2 = WXT + 64 * SW;                // [64 j][136 n] (read via trans)
        float*  ws  = (float*)(Bs2 + 64 * CW);      // [64]

        const uint32_t WxB = smem_u32(WXT), Bs2B = smem_u32(Bs2);
        const uint32_t aT_off = (uint32_t)((mw * 16 + (lane & 15)) * SW + ((lane >> 4) & 1) * 8) * 2;
        // trans B-operand from Bs2[j][n]: rows=j, cols=n
        const uint32_t bTt_off = (uint32_t)(((lane & 7) + ((lane >> 3) & 1) * 8) * CW
                                            + nw * 64 + ((lane >> 4) & 1) * 8) * 2;

        const float cum_last = d_cum[(size_t)(c * CSz + CSz - 1) * Hh + h];

        float acc[8][4];
#pragma unroll
        for (int i = 0; i < 8; ++i)
#pragma unroll
            for (int j = 0; j < 4; ++j) acc[i][j] = 0.f;

        for (int j0 = 0; j0 < CSz; j0 += 64) {
            __syncthreads();
#pragma unroll
            for (int rep = 0; rep < 4; ++rep) {
                int idx = tid + rep * 256;
                int r = idx >> 4, qn = idx & 15;
                *(float4*)&Xsf[r * 68 + qn * 4] =
                    *(const float4*)&d_xbc[(size_t)(c * CSz + j0 + r) * CONVC + h * Pp + qn * 4];
            }
#pragma unroll
            for (int rep = 0; rep < 4; ++rep) {
                int idx = tid + rep * 256;
                int r = idx >> 4, qq = idx & 15;
                *(uint4*)&Bs2[r * CW + qq * 8] =
                    *(const uint4*)&d_xbch[(size_t)(c * CSz + j0 + r) * CONVC + INTERC + g * Nn + qq * 8];
            }
            if (tid < 64) {
                int l = c * CSz + j0 + tid;
                ws[tid] = d_dt[(size_t)l * Hh + h] * __expf(cum_last - d_cum[(size_t)l * Hh + h]);
            }
            __syncthreads();

            // WXT[p][j] = w_j * x[j][p]
#pragma unroll
            for (int rep = 0; rep < 4; ++rep) {
                int idx = tid + rep * 256;
                int jb = idx >> 5, pb = idx & 31;
                float2 a0 = *(const float2*)&Xsf[(2 * jb) * 68 + 2 * pb];
                float2 a1 = *(const float2*)&Xsf[(2 * jb + 1) * 68 + 2 * pb];
                float w0 = ws[2 * jb], w1 = ws[2 * jb + 1];
                *(__half2*)&WXT[(2 * pb) * SW + 2 * jb]     = __floats2half2_rn(w0 * a0.x, w1 * a1.x);
                *(__half2*)&WXT[(2 * pb + 1) * SW + 2 * jb] = __floats2half2_rn(w0 * a0.y, w1 * a1.y);
            }
            __syncthreads();

#pragma unroll
            for (int ks = 0; ks < 4; ++ks) {
                const uint32_t kadd = (uint32_t)ks * 32;               // A: 16 j-halves
                uint32_t af[4];
                ldm_x4(af, WxB + aT_off + kadd);
                uint32_t bf[4][4];
                const uint32_t jrow = (uint32_t)(ks * 16 * CW) * 2;    // B: 16 j-rows
#pragma unroll
                for (int nb = 0; nb < 4; ++nb)
                    ldm_x4_t(bf[nb], Bs2B + bTt_off + jrow + (uint32_t)(nb * 16) * 2);
#pragma unroll
                for (int ni = 0; ni < 8; ++ni)
                    mma_f16(acc[ni], af, &bf[ni >> 1][(ni & 1) * 2]);
            }
        }

        const int p0 = mw * 16 + gq;
#pragma unroll
        for (int ni = 0; ni < 8; ++ni) {
            int nn = nw * 64 + ni * 8 + 2 * q;
            size_t b0 = ((size_t)(c * Hh + h) * Pp + p0) * Nn + nn;
            size_t b1 = ((size_t)(c * Hh + h) * Pp + p0 + 8) * Nn + nn;
            *(float2*)&d_st[b0] = make_float2(acc[ni][0], acc[ni][1]);
            *(float2*)&d_st[b1] = make_float2(acc[ni][2], acc[ni][3]);
        }
    }
}

// ---------------- inter-chunk scan (float2, writes fp16 prev) ----------------
__global__ void __launch_bounds__(256)
ssd_scan_k() {
    int idx2 = blockIdx.x * 256 + threadIdx.x;
    if (idx2 >= Hh * Pp * Nn / 2) return;
    int idx = idx2 * 2;
    int h = idx / (Pp * Nn);
    float2 carry = make_float2(0.f, 0.f);
#pragma unroll
    for (int c = 0; c < NC; ++c) {
        __half2 ph = __floats2half2_rn(carry.x, carry.y);
        *(__half2*)&d_prevh[(size_t)c * Hh * Pp * Nn + idx] = ph;
        float cdec = __expf(d_cum[(size_t)(c * CSz + CSz - 1) * Hh + h]);
        float2 st = *(const float2*)&d_st[(size_t)c * Hh * Pp * Nn + idx];
        carry.x = cdec * carry.x + st.x;
        carry.y = cdec * carry.y + st.y;
    }
}

// ---------------- inter-chunk output (fp16 MMA) + D*x ----------------
__global__ void __launch_bounds__(256)
ssd_inter_k(const float* __restrict__ Dp) {
    __shared__ __align__(16) __half Cs[64 * CW];
    __shared__ __align__(16) __half Ph[64 * CW];
    __shared__ float cum_i[64];

    const int it = blockIdx.x, h = blockIdx.y, c = blockIdx.z;
    const int g = h >> 4;
    const int tid = threadIdx.x;
    const int wid = tid >> 5, lane = tid & 31;
    const int gq = lane >> 2, q = lane & 3;
    const int mw = wid >> 1;
    const int nw = wid & 1;

    const int li0 = c * CSz + it * 64;
    const int ccol = INTERC + Gg * Nn + g * Nn;
    const size_t pbase = ((size_t)(c * Hh + h) * Pp) * Nn;

#pragma unroll
    for (int rep = 0; rep < 4; ++rep) {
        int idx = tid + rep * 256;
        int r = idx >> 4, qq = idx & 15;
        *(uint4*)&Cs[r * CW + qq * 8] =
            *(const uint4*)&d_xbch[(size_t)(li0 + r) * CONVC + ccol + qq * 8];
        *(uint4*)&Ph[r * CW + qq * 8] =
            *(const uint4*)&d_prevh[pbase + (size_t)r * Nn + qq * 8];
    }
    if (tid < 64) cum_i[tid] = d_cum[(size_t)(li0 + tid) * Hh + h];
    __syncthreads();

    const uint32_t CsB = smem_u32(Cs), PhB = smem_u32(Ph);
    const uint32_t a_off = (uint32_t)((mw * 16 + (lane & 15)) * CW + ((lane >> 4) & 1) * 8) * 2;
    const uint32_t b_off = (uint32_t)((nw * 32 + (lane & 7) + ((lane >> 4) & 1) * 8) * CW + ((lane >> 3) & 1) * 8) * 2;

    float acc[4][4];
#pragma unroll
    for (int i = 0; i < 4; ++i)
#pragma unroll
        for (int j = 0; j < 4; ++j) acc[i][j] = 0.f;

#pragma unroll
    for (int ks = 0; ks < 8; ++ks) {
        const uint32_t kadd = (uint32_t)ks * 32;
        uint32_t af[4];
        ldm_x4(af, CsB + a_off + kadd);
        uint32_t bf[2][4];
        ldm_x4(bf[0], PhB + b_off + kadd);
        ldm_x4(bf[1], PhB + b_off + (uint32_t)(16 * CW) * 2 + kadd);
#pragma unroll
        for (int ni = 0; ni < 4; ++ni)
            mma_f16(acc[ni], af, &bf[ni >> 1][(ni & 1) * 2]);
    }

    const int i0 = mw * 16 + gq;
    const float esc0 = __expf(cum_i[i0]);
    const float esc1 = __expf(cum_i[i0 + 8]);
    const float Dh = Dp[h];
#pragma unroll
    for (int ni = 0; ni < 4; ++ni) {
        int p = nw * 32 + ni * 8 + 2 * q;
        size_t y0 = (size_t)(li0 + i0) * INTERC + h * Pp + p;
        size_t y1 = (size_t)(li0 + i0 + 8) * INTERC + h * Pp + p;
        size_t x0 = (size_t)(li0 + i0) * CONVC + h * Pp + p;
        size_t x1 = (size_t)(li0 + i0 + 8) * CONVC + h * Pp + p;
        float2 yv0 = *(const float2*)&d_y[y0];
        float2 yv1 = *(const float2*)&d_y[y1];
        float2 xv0 = *(const float2*)&d_xbc[x0];
        float2 xv1 = *(const float2*)&d_xbc[x1];
        yv0.x += esc0 * acc[ni][0] + Dh * xv0.x;
        yv0.y += esc0 * acc[ni][1] + Dh * xv0.y;
        yv1.x += esc1 * acc[ni][2] + Dh * xv1.x;
        yv1.y += esc1 * acc[ni][3] + Dh * xv1.y;
        *(float2*)&d_y[y0] = yv0;
        *(float2*)&d_y[y1] = yv1;
    }
}

// ---------------- gated RMS group-norm (writes fp16 d_gh) ----------------
__global__ void __launch_bounds__(256)
gated_norm_k(const float* __restrict__ norm_w) {
    const int l = blockIdx.x, grp = blockIdx.y;
    const int tid = threadIdx.x;
    float v[4];
    float ss = 0.f;
#pragma unroll
    for (int i = 0; i < 4; ++i) {
        int col = grp * GSZ + tid + i * 256;
        float gate = d_proj[(size_t)l * PROJC + col];
        float yv = d_y[(size_t)l * INTERC + col];
        float sg = gate / (1.f + __expf(-gate));
        v[i] = yv * sg;
        ss += v[i] * v[i];
    }
#pragma unroll
    for (int off = 16; off; off >>= 1) ss += __shfl_xor_sync(0xffffffffu, ss, off);
    __shared__ float red[8];
    if ((tid & 31) == 0) red[tid >> 5] = ss;
    __syncthreads();
    float tot = red[0] + red[1] + red[2] + red[3] + red[4] + red[5] + red[6] + red[7];
    float rs = rsqrtf(tot / (float)GSZ + EPSf);
#pragma unroll
    for (int i = 0; i < 4; ++i) {
        int col = grp * GSZ + tid + i * 256;
        d_gh[(size_t)l * INTERC + col] = __float2half_rn(v[i] * rs * norm_w[col]);
    }
}

// ---------------- launch ----------------
extern "C" void kernel_launch(void* const* d_in, const int* in_sizes, int n_in,
                              void* d_out, int out_size) {
    const float* input     = (const float*)d_in[0];
    const float* in_proj_w = (const float*)d_in[1];
    const float* conv_w    = (const float*)d_in[2];
    const float* conv_b    = (const float*)d_in[3];
    const float* dt_bias   = (const float*)d_in[4];
    const float* A_log     = (const float*)d_in[5];
    const float* Dp        = (const float*)d_in[6];
    const float* norm_w    = (const float*)d_in[7];
    const float* out_w     = (const float*)d_in[8];
    float* out = (float*)d_out;

    cudaFuncSetAttribute(gemm1_mma_k, cudaFuncAttributeMaxDynamicSharedMemorySize, GM_SMEM);
    cudaFuncSetAttribute(gemm2_mma_k, cudaFuncAttributeMaxDynamicSharedMemorySize, GM_SMEM);
    cudaFuncSetAttribute(ssd_intra_states_k, cudaFuncAttributeMaxDynamicSharedMemorySize, IT_SMEM2);

    __half* ha;  cudaGetSymbolAddress((void**)&ha,  d_ha);
    __half* hb1; cudaGetSymbolAddress((void**)&hb1, d_hb1);
    __half* hb2; cudaGetSymbolAddress((void**)&hb2, d_hb2);

    // 0. fp16 pre-convert (ha + hb1; hb2 folded into conv_dt)
    cvt_all_k<<<4096, 256>>>((const float4*)input, (uint2*)ha,
                             (const float4*)in_proj_w, (uint2*)hb1);

    // 1. in_proj GEMM (fp16 mma)
    gemm1_mma_k<<<dim3(Lq / BMt, PROJC / BNt), 256, GM_SMEM>>>();
    // 2. fused conv+SiLU || dt warp-scan || hb2 convert
    conv_dt_k<<<dim3(26, 128), 256>>>(conv_w, conv_b, dt_bias, A_log,
                                      (const float4*)out_w, (uint2*)hb2);
    // 3. fused intra-chunk (fp16 MMA, trans-ldmatrix) || chunk-states (fp16 MMA, trans-ldmatrix)
    ssd_intra_states_k<<<dim3(5, Hh, NC), 256, IT_SMEM2>>>();
    // 4. inter-chunk sequential scan -> d_prevh (fp16)
    ssd_scan_k<<<(Hh * Pp * Nn / 2 + 255) / 256, 256>>>();
    // 5. inter-chunk contribution (fp16 MMA) + D*x -> d_y (final)
    ssd_inter_k<<<dim3(4, Hh, NC), 256>>>(Dp);
    // 6. gated RMS group-norm -> d_gh (fp16)
    gated_norm_k<<<dim3(Lq, Gg), 256>>>(norm_w);
    // 7. out GEMM (fp16 mma)
    gemm2_mma_k<<<dim3(Lq / BMt, HIDm / BNt), 256, GM_SMEM>>>(out);
}